// round 5
// baseline (speedup 1.0000x reference)
#include <cuda_runtime.h>
#include <cub/cub.cuh>

// Problem constants
#define NB_   80000      // B*N nodes layer 0/1
#define BGR_  8          // graphs
#define NPG_  10000      // nodes per graph (layer 1)
#define EDG_  640000     // edges
#define CC_   128        // channels
#define FF_   64         // input features
#define KK1_  6000       // kept after pool1 (per graph)
#define NB1_  48000      // B*KK1
#define KK2_  3600       // kept after pool2 (per graph)
#define NB2_  28800      // B*KK2

#define INVALID_KEY 0x1FFFF   // sorts after any node id (17-bit sort)
#define SORT_BITS   17

// ---------------- static device scratch (no allocs allowed) ----------------
__device__ float g_bufA[NB_ * CC_];
__device__ float g_bufB[NB_ * CC_];
__device__ float g_bufC[NB_ * CC_];
__device__ float g_scores[NB_];
__device__ float g_skey[NB_];
__device__ int   g_iota[NB_];
__device__ int   g_sidx[NB_];
__device__ int   g_newid[NB_];
__device__ int   g_src2[EDG_];
__device__ int   g_dst2[EDG_];
__device__ unsigned char g_mask2[EDG_];
__device__ int   g_offs[9];
__device__ float g_out1[BGR_ * CC_];
__device__ float g_out2[BGR_ * CC_];
__device__ int   g_keys[EDG_];
__device__ int   g_keysB[EDG_];
__device__ int   g_vals[EDG_];
__device__ int   g_valsB[EDG_];
__device__ int   g_counts[NB_];
__device__ int   g_rowptr[NB_ + 1];
__device__ unsigned char g_cubtmp[1u << 25];  // 32 MB cub temp

// ---------------- XLA-GPU (MLIR math polynomial approximation) tanh -------
__device__ __forceinline__ float xla_tanh(float ax) {
    const float plus_clamp  = 7.99881172180175781f;
    const float minus_clamp = -7.99881172180175781f;
    const float tiny = 0.0004f;
    const float alpha_1  = 4.89352455891786e-03f;
    const float alpha_3  = 6.37261928875436e-04f;
    const float alpha_5  = 1.48572235717979e-05f;
    const float alpha_7  = 5.12229709037114e-08f;
    const float alpha_9  = -8.60467152213735e-11f;
    const float alpha_11 = 2.00018790482477e-13f;
    const float alpha_13 = -2.76076847742355e-16f;
    const float beta_0 = 4.89352518554385e-03f;
    const float beta_2 = 2.26843463243900e-03f;
    const float beta_4 = 1.18534705686654e-04f;
    const float beta_6 = 1.19825839466702e-06f;

    float x = fminf(fmaxf(ax, minus_clamp), plus_clamp);
    float x2 = x * x;
    float p = fmaf(x2, alpha_13, alpha_11);
    p = fmaf(x2, p, alpha_9);
    p = fmaf(x2, p, alpha_7);
    p = fmaf(x2, p, alpha_5);
    p = fmaf(x2, p, alpha_3);
    p = fmaf(x2, p, alpha_1);
    p = x * p;
    float q = fmaf(x2, beta_6, beta_4);
    q = fmaf(x2, q, beta_2);
    q = fmaf(x2, q, beta_0);
    float r = p / q;
    return (fabsf(ax) < tiny) ? ax : r;
}

// ---------------- packed f32x2 helpers (sm_103a FFMA2) --------------------
__device__ __forceinline__ void ffma2(unsigned long long& d,
                                      unsigned long long a, unsigned long long b) {
    asm("fma.rn.f32x2 %0, %1, %2, %0;" : "+l"(d) : "l"(a), "l"(b));
}
__device__ __forceinline__ unsigned long long bcast2(float a) {
    unsigned long long r;
    unsigned int ai = __float_as_uint(a);
    asm("mov.b64 %0, {%1, %1};" : "=l"(r) : "r"(ai));
    return r;
}
__device__ __forceinline__ void unpack2(unsigned long long v, float& lo, float& hi) {
    unsigned int l, h;
    asm("mov.b64 {%0, %1}, %2;" : "=r"(l), "=r"(h) : "l"(v));
    lo = __uint_as_float(l);
    hi = __uint_as_float(h);
}

// ---------------- GEMM: [M x K] @ [K x 128] + bias (+relu) ----------------
// 128x128 tile, 256 threads, 8x8 microtile, packed FFMA2 accumulation.
// Per-element accumulation is a k-sequential IEEE fp32 FMA chain: numerics
// identical to the scalar version (FFMA2 = 2 independent FFMA lanes).
template <int K, bool RELU>
__global__ void __launch_bounds__(256) gemm_kernel(const float* __restrict__ A,
                                                   const float* __restrict__ W,
                                                   const float* __restrict__ bias,
                                                   float* __restrict__ out) {
    __shared__ float As[128][36];   // row-major, padded
    __shared__ float Bs[32][128];

    const int tid  = threadIdx.x;
    const int row0 = blockIdx.x * 128;
    const int r0 = (tid >> 4) * 8;   // 0..120
    const int c0 = (tid & 15) * 8;   // 0..120

    unsigned long long acc[8][4];
#pragma unroll
    for (int i = 0; i < 8; i++)
#pragma unroll
        for (int j = 0; j < 4; j++) acc[i][j] = 0ull;

    for (int k0 = 0; k0 < K; k0 += 32) {
        // load A tile 128x32 (1024 float4, 4 per thread)
#pragma unroll
        for (int it = 0; it < 4; ++it) {
            const int idx = tid + it * 256;
            const int r  = idx >> 3;
            const int k4 = (idx & 7) * 4;
            *(float4*)&As[r][k4] = *(const float4*)(A + (size_t)(row0 + r) * K + k0 + k4);
        }
        // load B tile 32x128 (1024 float4, 4 per thread)
#pragma unroll
        for (int it = 0; it < 4; ++it) {
            const int idx = tid + it * 256;
            const int k  = idx >> 5;
            const int c4 = (idx & 31) * 4;
            *(float4*)&Bs[k][c4] = *(const float4*)(W + (size_t)(k0 + k) * 128 + c4);
        }
        __syncthreads();
#pragma unroll
        for (int kk = 0; kk < 32; ++kk) {
            const ulonglong2 b01 = *(const ulonglong2*)&Bs[kk][c0];
            const ulonglong2 b23 = *(const ulonglong2*)&Bs[kk][c0 + 4];
#pragma unroll
            for (int i = 0; i < 8; i++) {
                const unsigned long long ap = bcast2(As[r0 + i][kk]);
                ffma2(acc[i][0], ap, b01.x);
                ffma2(acc[i][1], ap, b01.y);
                ffma2(acc[i][2], ap, b23.x);
                ffma2(acc[i][3], ap, b23.y);
            }
        }
        __syncthreads();
    }

    float bv[8];
#pragma unroll
    for (int j = 0; j < 8; j++) bv[j] = bias[c0 + j];

#pragma unroll
    for (int i = 0; i < 8; i++) {
        float v[8];
        unpack2(acc[i][0], v[0], v[1]);
        unpack2(acc[i][1], v[2], v[3]);
        unpack2(acc[i][2], v[4], v[5]);
        unpack2(acc[i][3], v[6], v[7]);
        float4 o0, o1;
        o0.x = v[0] + bv[0]; o0.y = v[1] + bv[1];
        o0.z = v[2] + bv[2]; o0.w = v[3] + bv[3];
        o1.x = v[4] + bv[4]; o1.y = v[5] + bv[5];
        o1.z = v[6] + bv[6]; o1.w = v[7] + bv[7];
        if (RELU) {
            o0.x = fmaxf(o0.x, 0.f); o0.y = fmaxf(o0.y, 0.f);
            o0.z = fmaxf(o0.z, 0.f); o0.w = fmaxf(o0.w, 0.f);
            o1.x = fmaxf(o1.x, 0.f); o1.y = fmaxf(o1.y, 0.f);
            o1.z = fmaxf(o1.z, 0.f); o1.w = fmaxf(o1.w, 0.f);
        }
        float* orow = out + (size_t)(row0 + r0 + i) * 128 + c0;
        *(float4*)orow = o0;
        *(float4*)(orow + 4) = o1;
    }
}

// ---------------- CSR build helpers ----------------
__global__ void fill0_kernel(int* a, int n) {
    int i = blockIdx.x * blockDim.x + threadIdx.x;
    if (i < n) a[i] = 0;
}
__global__ void build_keys_kernel(const int* __restrict__ dst, const int* __restrict__ src,
                                  const unsigned char* __restrict__ mask,
                                  int* __restrict__ keys, int* __restrict__ vals,
                                  int* __restrict__ counts, int nE) {
    int e = blockIdx.x * blockDim.x + threadIdx.x;
    if (e >= nE) return;
    const bool valid = mask ? (mask[e] != 0) : true;
    keys[e] = valid ? dst[e] : INVALID_KEY;
    vals[e] = src[e];
    if (valid) atomicAdd(&counts[dst[e]], 1);
}
__global__ void set_last_kernel(int* rowptr, const int* counts, int n) {
    if (threadIdx.x == 0) rowptr[n] = rowptr[n - 1] + counts[n - 1];
}

// ---------------- deterministic aggregation (warp per node) ----------------
template <bool ADD_SELF>
__global__ void agg_kernel(const float* __restrict__ x,
                           const int* __restrict__ rowptr,
                           const int* __restrict__ srcs,
                           float* __restrict__ out, int n) {
    const int node = blockIdx.x * 8 + (threadIdx.x >> 5);
    if (node >= n) return;
    const int lane = threadIdx.x & 31;
    const int b = rowptr[node], e = rowptr[node + 1];
    float4 acc = make_float4(0.f, 0.f, 0.f, 0.f);
    for (int i = b; i < e; ++i) {
        const int s = srcs[i];
        const float4 v = *(const float4*)(x + (size_t)s * CC_ + lane * 4);
        acc.x += v.x; acc.y += v.y; acc.z += v.z; acc.w += v.w;
    }
    if (ADD_SELF) {
        const float4 xv = *(const float4*)(x + (size_t)node * CC_ + lane * 4);
        acc.x = xv.x + acc.x; acc.y = xv.y + acc.y;
        acc.z = xv.z + acc.z; acc.w = xv.w + acc.w;
    }
    *(float4*)(out + (size_t)node * CC_ + lane * 4) = acc;
}

// ---------------- SAGPool score, sequential dots (thread per node) --------
__global__ void score_kernel(const float* __restrict__ agg, const float* __restrict__ x,
                             const float* __restrict__ Wrel, const float* __restrict__ brel,
                             const float* __restrict__ Wroot,
                             float* __restrict__ scores, int n) {
    const int node = blockIdx.x * blockDim.x + threadIdx.x;
    if (node >= n) return;
    const float* a  = agg + (size_t)node * CC_;
    const float* xx = x + (size_t)node * CC_;
    float t1 = 0.f;
#pragma unroll 16
    for (int c = 0; c < CC_; ++c) t1 = fmaf(a[c], Wrel[c], t1);
    t1 = t1 + brel[0];
    float t2 = 0.f;
#pragma unroll 16
    for (int c = 0; c < CC_; ++c) t2 = fmaf(xx[c], Wroot[c], t2);
    scores[node] = xla_tanh(t1 + t2);
}

// ---------------- small helpers ----------------
__global__ void iota_kernel(int* a, int n) {
    int i = blockIdx.x * blockDim.x + threadIdx.x;
    if (i < n) a[i] = i;
}
__global__ void filln1_kernel(int* a, int n) {
    int i = blockIdx.x * blockDim.x + threadIdx.x;
    if (i < n) a[i] = -1;
}
__global__ void offs_kernel(int* offs, int npg) {
    int t = threadIdx.x;
    if (t < 9) offs[t] = t * npg;
}

// ---------------- selection/gather after sort (1 warp / kept node) -------
__global__ void select_kernel(const float* __restrict__ skey, const int* __restrict__ sidx,
                              const float* __restrict__ xin, float* __restrict__ xout,
                              int* __restrict__ newid, int npg, int k) {
    const int j = blockIdx.x * 8 + (threadIdx.x >> 5);
    if (j >= BGR_ * k) return;
    const int g = j / k, jj = j - g * k;
    const int srcpos = g * npg + jj;
    const int orig = sidx[srcpos];
    const float val = skey[srcpos];
    const int lane = threadIdx.x & 31;
    float4 v = *(const float4*)(xin + (size_t)orig * CC_ + lane * 4);
    v.x *= val; v.y *= val; v.z *= val; v.w *= val;
    *(float4*)(xout + (size_t)j * CC_ + lane * 4) = v;
    if (lane == 0) newid[orig] = j;
}

// ---------------- edge remap after pooling ----------------
__global__ void remap_kernel(const int* __restrict__ src, const int* __restrict__ dst,
                             const int* __restrict__ newid,
                             int* __restrict__ src2, int* __restrict__ dst2,
                             unsigned char* __restrict__ mask2) {
    const int e = blockIdx.x * blockDim.x + threadIdx.x;
    if (e >= EDG_) return;
    const int s = newid[src[e]];
    const int d = newid[dst[e]];
    const bool ok = (s >= 0) && (d >= 0);
    src2[e] = s; dst2[e] = d; mask2[e] = ok ? 1 : 0;
}

// ---------------- per-graph mean pooling ----------------
__global__ void mean_kernel(const float* __restrict__ x, float* __restrict__ out, int k) {
    __shared__ float col[CC_];
    const int b = blockIdx.x, tid = threadIdx.x;
    if (tid < CC_) col[tid] = 0.f;
    __syncthreads();
    float s = 0.f;
    const float* base = x + (size_t)b * k * CC_;
    const int total = k * CC_;
    for (int idx = tid; idx < total; idx += 256) s += base[idx];
    atomicAdd(&col[tid & 127], s);
    __syncthreads();
    if (tid < CC_) out[b * CC_ + tid] = col[tid] / (float)k;
}

// ---------------- final MLP head (single block) ----------------
__global__ void head_kernel(const float* __restrict__ out1, const float* __restrict__ out2,
                            const float* __restrict__ Wg, const float* __restrict__ bg,
                            const float* __restrict__ Wr1, const float* __restrict__ br1,
                            const float* __restrict__ gg1, const float* __restrict__ be1,
                            const float* __restrict__ Wr2, const float* __restrict__ br2,
                            const float* __restrict__ gg2, const float* __restrict__ be2,
                            const float* __restrict__ Wout, float* __restrict__ out) {
    __shared__ float cat[8][256];
    __shared__ float gmat[8][128];
    __shared__ float r1[8][64];
    __shared__ float r2[8][32];
    const int tid = threadIdx.x;  // 256 threads
    for (int i = tid; i < 8 * 128; i += 256) {
        const int b = i >> 7, c = i & 127;
        cat[b][c]       = out1[i];
        cat[b][c + 128] = out2[i];
    }
    __syncthreads();
    const float inv = 1.0f / sqrtf(1.0f + 1e-5f);
    if (tid < 128) {
        for (int b = 0; b < 8; b++) {
            float s = 0.f;
            for (int k = 0; k < 256; k++) s = fmaf(cat[b][k], Wg[k * 128 + tid], s);
            gmat[b][tid] = s + bg[tid];
        }
    }
    __syncthreads();
    if (tid < 64) {
        for (int b = 0; b < 8; b++) {
            float s = 0.f;
            for (int k = 0; k < 128; k++) s = fmaf(gmat[b][k], Wr1[k * 64 + tid], s);
            s = (s + br1[tid]) * inv * gg1[tid] + be1[tid];
            r1[b][tid] = fmaxf(s, 0.f);
        }
    }
    __syncthreads();
    if (tid < 32) {
        for (int b = 0; b < 8; b++) {
            float s = 0.f;
            for (int k = 0; k < 64; k++) s = fmaf(r1[b][k], Wr2[k * 32 + tid], s);
            s = (s + br2[tid]) * inv * gg2[tid] + be2[tid];
            r2[b][tid] = fmaxf(s, 0.f);
        }
    }
    __syncthreads();
    if (tid < 32) {
        const int b = tid >> 2, j = tid & 3;
        float s = 0.f;
        for (int k = 0; k < 32; k++) s = fmaf(r2[b][k], Wout[k * 4 + j], s);
        out[b * 4 + j] = s;
    }
}

// ---------------- host orchestration ----------------
static void build_csr(const int* dst, const int* src, const unsigned char* mask,
                      int* keys, int* keysB, int* vals, int* valsB,
                      int* counts, int* rowptr, unsigned char* cubtmp, int n_nodes) {
    fill0_kernel<<<(n_nodes + 255) / 256, 256>>>(counts, n_nodes);
    build_keys_kernel<<<EDG_ / 256, 256>>>(dst, src, mask, keys, vals, counts, EDG_);
    size_t tmp = 0;
    cub::DeviceScan::ExclusiveSum(nullptr, tmp, counts, rowptr, n_nodes);
    if (tmp > sizeof(g_cubtmp)) tmp = sizeof(g_cubtmp);
    cub::DeviceScan::ExclusiveSum((void*)cubtmp, tmp, counts, rowptr, n_nodes);
    set_last_kernel<<<1, 32>>>(rowptr, counts, n_nodes);
    size_t tmp2 = 0;
    cub::DeviceRadixSort::SortPairs(nullptr, tmp2, keys, keysB, vals, valsB, EDG_, 0, SORT_BITS);
    if (tmp2 > sizeof(g_cubtmp)) tmp2 = sizeof(g_cubtmp);
    cub::DeviceRadixSort::SortPairs((void*)cubtmp, tmp2, keys, keysB, vals, valsB, EDG_, 0, SORT_BITS);
}

extern "C" void kernel_launch(void* const* d_in, const int* in_sizes, int n_in,
                              void* d_out, int out_size) {
    const float* x    = (const float*)d_in[0];
    const int*   ei   = (const int*)d_in[1];
    const int*   src  = ei;
    const int*   dst  = ei + EDG_;
    const float* W0   = (const float*)d_in[3];
    const float* b0   = (const float*)d_in[4];
    const float* W1a  = (const float*)d_in[5];
    const float* b1a  = (const float*)d_in[6];
    const float* W1b  = (const float*)d_in[7];
    const float* b1b  = (const float*)d_in[8];
    const float* Wrel1  = (const float*)d_in[9];
    const float* brel1  = (const float*)d_in[10];
    const float* Wroot1 = (const float*)d_in[11];
    const float* W2a  = (const float*)d_in[12];
    const float* b2a  = (const float*)d_in[13];
    const float* W2b  = (const float*)d_in[14];
    const float* b2b  = (const float*)d_in[15];
    const float* Wrel2  = (const float*)d_in[16];
    const float* brel2  = (const float*)d_in[17];
    const float* Wroot2 = (const float*)d_in[18];
    const float* Wg   = (const float*)d_in[19];
    const float* bg   = (const float*)d_in[20];
    const float* Wr1  = (const float*)d_in[21];
    const float* br1  = (const float*)d_in[22];
    const float* gg1  = (const float*)d_in[23];
    const float* be1  = (const float*)d_in[24];
    const float* Wr2  = (const float*)d_in[25];
    const float* br2  = (const float*)d_in[26];
    const float* gg2  = (const float*)d_in[27];
    const float* be2  = (const float*)d_in[28];
    const float* Wout = (const float*)d_in[29];

    float *bufA, *bufB, *bufC, *scores, *skey, *o1, *o2;
    int *iota, *sidx, *newid, *src2, *dst2, *offs;
    int *keys, *keysB, *vals, *valsB, *counts, *rowptr;
    unsigned char *mask2, *cubtmp;
    cudaGetSymbolAddress((void**)&bufA, g_bufA);
    cudaGetSymbolAddress((void**)&bufB, g_bufB);
    cudaGetSymbolAddress((void**)&bufC, g_bufC);
    cudaGetSymbolAddress((void**)&scores, g_scores);
    cudaGetSymbolAddress((void**)&skey, g_skey);
    cudaGetSymbolAddress((void**)&iota, g_iota);
    cudaGetSymbolAddress((void**)&sidx, g_sidx);
    cudaGetSymbolAddress((void**)&newid, g_newid);
    cudaGetSymbolAddress((void**)&src2, g_src2);
    cudaGetSymbolAddress((void**)&dst2, g_dst2);
    cudaGetSymbolAddress((void**)&mask2, g_mask2);
    cudaGetSymbolAddress((void**)&offs, g_offs);
    cudaGetSymbolAddress((void**)&o1, g_out1);
    cudaGetSymbolAddress((void**)&o2, g_out2);
    cudaGetSymbolAddress((void**)&keys, g_keys);
    cudaGetSymbolAddress((void**)&keysB, g_keysB);
    cudaGetSymbolAddress((void**)&vals, g_vals);
    cudaGetSymbolAddress((void**)&valsB, g_valsB);
    cudaGetSymbolAddress((void**)&counts, g_counts);
    cudaGetSymbolAddress((void**)&rowptr, g_rowptr);
    cudaGetSymbolAddress((void**)&cubtmp, g_cubtmp);

    // ---- layer-1 CSR (all edges valid), deterministic edge order
    build_csr(dst, src, nullptr, keys, keysB, vals, valsB, counts, rowptr, cubtmp, NB_);

    // ---- stage 0: h0 = relu(x @ W0 + b0) -> bufA
    gemm_kernel<FF_, true><<<NB_ / 128, 256>>>(x, W0, b0, bufA);

    // ---- GIN layer 1: t = h0 + segsum(h0[src] -> dst) ; h1 = nn(t)
    agg_kernel<true><<<NB_ / 8, 256>>>(bufA, rowptr, valsB, bufB, NB_);
    gemm_kernel<CC_, true ><<<NB_ / 128, 256>>>(bufB, W1a, b1a, bufC);
    gemm_kernel<CC_, false><<<NB_ / 128, 256>>>(bufC, W1b, b1b, bufB);  // h1 = bufB

    // ---- SAGPool 1
    agg_kernel<false><<<NB_ / 8, 256>>>(bufB, rowptr, valsB, bufA, NB_);
    score_kernel<<<(NB_ + 255) / 256, 256>>>(bufA, bufB, Wrel1, brel1, Wroot1, scores, NB_);
    iota_kernel<<<(NB_ + 255) / 256, 256>>>(iota, NB_);
    offs_kernel<<<1, 32>>>(offs, NPG_);
    {
        size_t tmp = 0;
        cub::DeviceSegmentedRadixSort::SortPairsDescending(
            nullptr, tmp, scores, skey, iota, sidx, NB_, BGR_, offs, offs + 1);
        if (tmp > sizeof(g_cubtmp)) tmp = sizeof(g_cubtmp);
        cub::DeviceSegmentedRadixSort::SortPairsDescending(
            (void*)cubtmp, tmp, scores, skey, iota, sidx, NB_, BGR_, offs, offs + 1);
    }
    filln1_kernel<<<(NB_ + 255) / 256, 256>>>(newid, NB_);
    select_kernel<<<NB1_ / 8, 256>>>(skey, sidx, bufB, bufC, newid, NPG_, KK1_);  // h2 = bufC
    mean_kernel<<<BGR_, 256>>>(bufC, o1, KK1_);
    remap_kernel<<<EDG_ / 256, 256>>>(src, dst, newid, src2, dst2, mask2);

    // ---- layer-2 CSR (masked edges excluded), deterministic edge order
    build_csr(dst2, src2, mask2, keys, keysB, vals, valsB, counts, rowptr, cubtmp, NB1_);

    // ---- GIN layer 2
    agg_kernel<true><<<NB1_ / 8, 256>>>(bufC, rowptr, valsB, bufA, NB1_);
    gemm_kernel<CC_, true ><<<NB1_ / 128, 256>>>(bufA, W2a, b2a, bufB);
    gemm_kernel<CC_, false><<<NB1_ / 128, 256>>>(bufB, W2b, b2b, bufC);  // h3 = bufC

    // ---- SAGPool 2
    agg_kernel<false><<<NB1_ / 8, 256>>>(bufC, rowptr, valsB, bufA, NB1_);
    score_kernel<<<(NB1_ + 255) / 256, 256>>>(bufA, bufC, Wrel2, brel2, Wroot2, scores, NB1_);
    iota_kernel<<<(NB1_ + 255) / 256, 256>>>(iota, NB1_);
    offs_kernel<<<1, 32>>>(offs, KK1_);
    {
        size_t tmp = 0;
        cub::DeviceSegmentedRadixSort::SortPairsDescending(
            nullptr, tmp, scores, skey, iota, sidx, NB1_, BGR_, offs, offs + 1);
        if (tmp > sizeof(g_cubtmp)) tmp = sizeof(g_cubtmp);
        cub::DeviceSegmentedRadixSort::SortPairsDescending(
            (void*)cubtmp, tmp, scores, skey, iota, sidx, NB1_, BGR_, offs, offs + 1);
    }
    select_kernel<<<NB2_ / 8, 256>>>(skey, sidx, bufC, bufB, newid, KK1_, KK2_);  // h4 = bufB
    mean_kernel<<<BGR_, 256>>>(bufB, o2, KK2_);

    // ---- head
    head_kernel<<<1, 256>>>(o1, o2, Wg, bg, Wr1, br1, gg1, be1,
                            Wr2, br2, gg2, be2, Wout, (float*)d_out);
}

// round 6
// speedup vs baseline: 1.0060x; 1.0060x over previous
#include <cuda_runtime.h>
#include <cub/cub.cuh>

// Problem constants
#define NB_   80000      // B*N nodes layer 0/1
#define BGR_  8          // graphs
#define NPG_  10000      // nodes per graph (layer 1)
#define EDG_  640000     // edges
#define CC_   128        // channels
#define FF_   64         // input features
#define KK1_  6000       // kept after pool1 (per graph)
#define NB1_  48000      // B*KK1
#define KK2_  3600       // kept after pool2 (per graph)
#define NB2_  28800      // B*KK2

#define INVALID_KEY 0x1FFFF   // sorts after any node id (17-bit sort)
#define SORT_BITS   17

// ---------------- static device scratch (no allocs allowed) ----------------
__device__ float g_bufA[NB_ * CC_];
__device__ float g_bufB[NB_ * CC_];
__device__ float g_bufC[NB_ * CC_];
__device__ float g_scores[NB_];
__device__ float g_skey[NB_];
__device__ float g_srel[NB_];
__device__ float g_sroot[NB_];
__device__ int   g_iota[NB_];
__device__ int   g_sidx[NB_];
__device__ int   g_newid[NB_];
__device__ int   g_src2[EDG_];
__device__ int   g_dst2[EDG_];
__device__ unsigned char g_mask2[EDG_];
__device__ int   g_offs[9];
__device__ float g_out1[BGR_ * CC_];
__device__ float g_out2[BGR_ * CC_];
__device__ int   g_keys[EDG_];
__device__ int   g_keysB[EDG_];
__device__ int   g_vals[EDG_];
__device__ int   g_valsB[EDG_];
__device__ int   g_counts[NB_];
__device__ int   g_rowptr[NB_ + 1];
__device__ unsigned char g_cubtmp[1u << 25];  // 32 MB cub temp

// ---------------- XLA-GPU (MLIR math polynomial approximation) tanh -------
__device__ __forceinline__ float xla_tanh(float ax) {
    const float plus_clamp  = 7.99881172180175781f;
    const float minus_clamp = -7.99881172180175781f;
    const float tiny = 0.0004f;
    const float alpha_1  = 4.89352455891786e-03f;
    const float alpha_3  = 6.37261928875436e-04f;
    const float alpha_5  = 1.48572235717979e-05f;
    const float alpha_7  = 5.12229709037114e-08f;
    const float alpha_9  = -8.60467152213735e-11f;
    const float alpha_11 = 2.00018790482477e-13f;
    const float alpha_13 = -2.76076847742355e-16f;
    const float beta_0 = 4.89352518554385e-03f;
    const float beta_2 = 2.26843463243900e-03f;
    const float beta_4 = 1.18534705686654e-04f;
    const float beta_6 = 1.19825839466702e-06f;

    float x = fminf(fmaxf(ax, minus_clamp), plus_clamp);
    float x2 = x * x;
    float p = fmaf(x2, alpha_13, alpha_11);
    p = fmaf(x2, p, alpha_9);
    p = fmaf(x2, p, alpha_7);
    p = fmaf(x2, p, alpha_5);
    p = fmaf(x2, p, alpha_3);
    p = fmaf(x2, p, alpha_1);
    p = x * p;
    float q = fmaf(x2, beta_6, beta_4);
    q = fmaf(x2, q, beta_2);
    q = fmaf(x2, q, beta_0);
    float r = p / q;
    return (fabsf(ax) < tiny) ? ax : r;
}

// ---------------- GEMM: [M x K] @ [K x 128] + bias (+relu) ----------------
// 128x128 tile, 256 threads, 8x8 microtile, SCALAR k-sequential FMA
// (identical accumulation order to the R4 passing kernel).
template <int K, bool RELU>
__global__ void __launch_bounds__(256) gemm_kernel(const float* __restrict__ A,
                                                   const float* __restrict__ W,
                                                   const float* __restrict__ bias,
                                                   float* __restrict__ out) {
    __shared__ float As[128][36];   // padded stride (multiple of 4 -> aligned float4)
    __shared__ float Bs[32][128];

    const int tid  = threadIdx.x;
    const int row0 = blockIdx.x * 128;
    const int r0 = (tid >> 4) * 8;   // 0..120
    const int c0 = (tid & 15) * 8;   // 0..120

    float acc[8][8];
#pragma unroll
    for (int i = 0; i < 8; i++)
#pragma unroll
        for (int j = 0; j < 8; j++) acc[i][j] = 0.f;

    for (int k0 = 0; k0 < K; k0 += 32) {
        // load A tile 128x32 (1024 float4, 4 per thread)
#pragma unroll
        for (int it = 0; it < 4; ++it) {
            const int idx = tid + it * 256;
            const int r  = idx >> 3;
            const int k4 = (idx & 7) * 4;
            *(float4*)&As[r][k4] = *(const float4*)(A + (size_t)(row0 + r) * K + k0 + k4);
        }
        // load B tile 32x128 (1024 float4, 4 per thread)
#pragma unroll
        for (int it = 0; it < 4; ++it) {
            const int idx = tid + it * 256;
            const int k  = idx >> 5;
            const int c4 = (idx & 31) * 4;
            *(float4*)&Bs[k][c4] = *(const float4*)(W + (size_t)(k0 + k) * 128 + c4);
        }
        __syncthreads();
#pragma unroll
        for (int kk = 0; kk < 32; ++kk) {
            float bf[8];
            *(float4*)&bf[0] = *(const float4*)&Bs[kk][c0];
            *(float4*)&bf[4] = *(const float4*)&Bs[kk][c0 + 4];
            float af[8];
#pragma unroll
            for (int i = 0; i < 8; i++) af[i] = As[r0 + i][kk];
#pragma unroll
            for (int i = 0; i < 8; i++)
#pragma unroll
                for (int j = 0; j < 8; j++)
                    acc[i][j] = fmaf(af[i], bf[j], acc[i][j]);
        }
        __syncthreads();
    }

    float bv[8];
#pragma unroll
    for (int j = 0; j < 8; j++) bv[j] = bias[c0 + j];

#pragma unroll
    for (int i = 0; i < 8; i++) {
        float4 o0, o1;
        o0.x = acc[i][0] + bv[0]; o0.y = acc[i][1] + bv[1];
        o0.z = acc[i][2] + bv[2]; o0.w = acc[i][3] + bv[3];
        o1.x = acc[i][4] + bv[4]; o1.y = acc[i][5] + bv[5];
        o1.z = acc[i][6] + bv[6]; o1.w = acc[i][7] + bv[7];
        if (RELU) {
            o0.x = fmaxf(o0.x, 0.f); o0.y = fmaxf(o0.y, 0.f);
            o0.z = fmaxf(o0.z, 0.f); o0.w = fmaxf(o0.w, 0.f);
            o1.x = fmaxf(o1.x, 0.f); o1.y = fmaxf(o1.y, 0.f);
            o1.z = fmaxf(o1.z, 0.f); o1.w = fmaxf(o1.w, 0.f);
        }
        float* orow = out + (size_t)(row0 + r0 + i) * 128 + c0;
        *(float4*)orow = o0;
        *(float4*)(orow + 4) = o1;
    }
}

// ---------------- CSR build helpers ----------------
__global__ void fill0_kernel(int* a, int n) {
    int i = blockIdx.x * blockDim.x + threadIdx.x;
    if (i < n) a[i] = 0;
}
__global__ void build_keys_kernel(const int* __restrict__ dst, const int* __restrict__ src,
                                  const unsigned char* __restrict__ mask,
                                  int* __restrict__ keys, int* __restrict__ vals,
                                  int* __restrict__ counts, int nE) {
    int e = blockIdx.x * blockDim.x + threadIdx.x;
    if (e >= nE) return;
    const bool valid = mask ? (mask[e] != 0) : true;
    keys[e] = valid ? dst[e] : INVALID_KEY;
    vals[e] = src[e];
    if (valid) atomicAdd(&counts[dst[e]], 1);
}
__global__ void set_last_kernel(int* rowptr, const int* counts, int n) {
    if (threadIdx.x == 0) rowptr[n] = rowptr[n - 1] + counts[n - 1];
}

// ---------------- deterministic aggregation (warp per node) ----------------
template <bool ADD_SELF>
__global__ void agg_kernel(const float* __restrict__ x,
                           const int* __restrict__ rowptr,
                           const int* __restrict__ srcs,
                           float* __restrict__ out, int n) {
    const int node = blockIdx.x * 8 + (threadIdx.x >> 5);
    if (node >= n) return;
    const int lane = threadIdx.x & 31;
    const int b = rowptr[node], e = rowptr[node + 1];
    float4 acc = make_float4(0.f, 0.f, 0.f, 0.f);
    for (int i = b; i < e; ++i) {
        const int s = srcs[i];
        const float4 v = *(const float4*)(x + (size_t)s * CC_ + lane * 4);
        acc.x += v.x; acc.y += v.y; acc.z += v.z; acc.w += v.w;
    }
    if (ADD_SELF) {
        const float4 xv = *(const float4*)(x + (size_t)node * CC_ + lane * 4);
        acc.x = xv.x + acc.x; acc.y = xv.y + acc.y;
        acc.z = xv.z + acc.z; acc.w = xv.w + acc.w;
    }
    *(float4*)(out + (size_t)node * CC_ + lane * 4) = acc;
}

// ---------------- score pre-pass: srel = h.Wrel, sroot = h.Wroot ----------
// Sequential channel-order FMA dots (one thread per node).
__global__ void score_pre_kernel(const float* __restrict__ x,
                                 const float* __restrict__ Wrel,
                                 const float* __restrict__ Wroot,
                                 float* __restrict__ srel, float* __restrict__ sroot,
                                 int n) {
    const int node = blockIdx.x * blockDim.x + threadIdx.x;
    if (node >= n) return;
    const float* xx = x + (size_t)node * CC_;
    float t1 = 0.f, t2 = 0.f;
#pragma unroll 16
    for (int c = 0; c < CC_; ++c) t1 = fmaf(xx[c], Wrel[c], t1);
#pragma unroll 16
    for (int c = 0; c < CC_; ++c) t2 = fmaf(xx[c], Wroot[c], t2);
    srel[node] = t1;
    sroot[node] = t2;
}

// ---------------- scalar score aggregation + tanh -------------------------
// score = tanh((sum_{j->i} srel[j] + brel) + sroot[i]); linearity of dot.
__global__ void score_agg_kernel(const float* __restrict__ srel,
                                 const float* __restrict__ sroot,
                                 const float* __restrict__ brel,
                                 const int* __restrict__ rowptr,
                                 const int* __restrict__ srcs,
                                 float* __restrict__ scores, int n) {
    const int node = blockIdx.x * blockDim.x + threadIdx.x;
    if (node >= n) return;
    const int b = rowptr[node], e = rowptr[node + 1];
    float s = 0.f;
    for (int i = b; i < e; ++i) s += srel[srcs[i]];
    scores[node] = xla_tanh((s + brel[0]) + sroot[node]);
}

// ---------------- small helpers ----------------
__global__ void iota_kernel(int* a, int n) {
    int i = blockIdx.x * blockDim.x + threadIdx.x;
    if (i < n) a[i] = i;
}
__global__ void filln1_kernel(int* a, int n) {
    int i = blockIdx.x * blockDim.x + threadIdx.x;
    if (i < n) a[i] = -1;
}
__global__ void offs_kernel(int* offs, int npg) {
    int t = threadIdx.x;
    if (t < 9) offs[t] = t * npg;
}

// ---------------- selection/gather after sort (1 warp / kept node) -------
__global__ void select_kernel(const float* __restrict__ skey, const int* __restrict__ sidx,
                              const float* __restrict__ xin, float* __restrict__ xout,
                              int* __restrict__ newid, int npg, int k) {
    const int j = blockIdx.x * 8 + (threadIdx.x >> 5);
    if (j >= BGR_ * k) return;
    const int g = j / k, jj = j - g * k;
    const int srcpos = g * npg + jj;
    const int orig = sidx[srcpos];
    const float val = skey[srcpos];
    const int lane = threadIdx.x & 31;
    float4 v = *(const float4*)(xin + (size_t)orig * CC_ + lane * 4);
    v.x *= val; v.y *= val; v.z *= val; v.w *= val;
    *(float4*)(xout + (size_t)j * CC_ + lane * 4) = v;
    if (lane == 0) newid[orig] = j;
}

// ---------------- edge remap after pooling ----------------
__global__ void remap_kernel(const int* __restrict__ src, const int* __restrict__ dst,
                             const int* __restrict__ newid,
                             int* __restrict__ src2, int* __restrict__ dst2,
                             unsigned char* __restrict__ mask2) {
    const int e = blockIdx.x * blockDim.x + threadIdx.x;
    if (e >= EDG_) return;
    const int s = newid[src[e]];
    const int d = newid[dst[e]];
    const bool ok = (s >= 0) && (d >= 0);
    src2[e] = s; dst2[e] = d; mask2[e] = ok ? 1 : 0;
}

// ---------------- per-graph mean pooling ----------------
__global__ void mean_kernel(const float* __restrict__ x, float* __restrict__ out, int k) {
    __shared__ float col[CC_];
    const int b = blockIdx.x, tid = threadIdx.x;
    if (tid < CC_) col[tid] = 0.f;
    __syncthreads();
    float s = 0.f;
    const float* base = x + (size_t)b * k * CC_;
    const int total = k * CC_;
    for (int idx = tid; idx < total; idx += 256) s += base[idx];
    atomicAdd(&col[tid & 127], s);
    __syncthreads();
    if (tid < CC_) out[b * CC_ + tid] = col[tid] / (float)k;
}

// ---------------- final MLP head (single block) ----------------
__global__ void head_kernel(const float* __restrict__ out1, const float* __restrict__ out2,
                            const float* __restrict__ Wg, const float* __restrict__ bg,
                            const float* __restrict__ Wr1, const float* __restrict__ br1,
                            const float* __restrict__ gg1, const float* __restrict__ be1,
                            const float* __restrict__ Wr2, const float* __restrict__ br2,
                            const float* __restrict__ gg2, const float* __restrict__ be2,
                            const float* __restrict__ Wout, float* __restrict__ out) {
    __shared__ float cat[8][256];
    __shared__ float gmat[8][128];
    __shared__ float r1[8][64];
    __shared__ float r2[8][32];
    const int tid = threadIdx.x;  // 256 threads
    for (int i = tid; i < 8 * 128; i += 256) {
        const int b = i >> 7, c = i & 127;
        cat[b][c]       = out1[i];
        cat[b][c + 128] = out2[i];
    }
    __syncthreads();
    const float inv = 1.0f / sqrtf(1.0f + 1e-5f);
    if (tid < 128) {
        for (int b = 0; b < 8; b++) {
            float s = 0.f;
            for (int k = 0; k < 256; k++) s = fmaf(cat[b][k], Wg[k * 128 + tid], s);
            gmat[b][tid] = s + bg[tid];
        }
    }
    __syncthreads();
    if (tid < 64) {
        for (int b = 0; b < 8; b++) {
            float s = 0.f;
            for (int k = 0; k < 128; k++) s = fmaf(gmat[b][k], Wr1[k * 64 + tid], s);
            s = (s + br1[tid]) * inv * gg1[tid] + be1[tid];
            r1[b][tid] = fmaxf(s, 0.f);
        }
    }
    __syncthreads();
    if (tid < 32) {
        for (int b = 0; b < 8; b++) {
            float s = 0.f;
            for (int k = 0; k < 64; k++) s = fmaf(r1[b][k], Wr2[k * 32 + tid], s);
            s = (s + br2[tid]) * inv * gg2[tid] + be2[tid];
            r2[b][tid] = fmaxf(s, 0.f);
        }
    }
    __syncthreads();
    if (tid < 32) {
        const int b = tid >> 2, j = tid & 3;
        float s = 0.f;
        for (int k = 0; k < 32; k++) s = fmaf(r2[b][k], Wout[k * 4 + j], s);
        out[b * 4 + j] = s;
    }
}

// ---------------- host orchestration ----------------
static void build_csr(const int* dst, const int* src, const unsigned char* mask,
                      int* keys, int* keysB, int* vals, int* valsB,
                      int* counts, int* rowptr, unsigned char* cubtmp, int n_nodes) {
    fill0_kernel<<<(n_nodes + 255) / 256, 256>>>(counts, n_nodes);
    build_keys_kernel<<<EDG_ / 256, 256>>>(dst, src, mask, keys, vals, counts, EDG_);
    size_t tmp = 0;
    cub::DeviceScan::ExclusiveSum(nullptr, tmp, counts, rowptr, n_nodes);
    if (tmp > sizeof(g_cubtmp)) tmp = sizeof(g_cubtmp);
    cub::DeviceScan::ExclusiveSum((void*)cubtmp, tmp, counts, rowptr, n_nodes);
    set_last_kernel<<<1, 32>>>(rowptr, counts, n_nodes);
    size_t tmp2 = 0;
    cub::DeviceRadixSort::SortPairs(nullptr, tmp2, keys, keysB, vals, valsB, EDG_, 0, SORT_BITS);
    if (tmp2 > sizeof(g_cubtmp)) tmp2 = sizeof(g_cubtmp);
    cub::DeviceRadixSort::SortPairs((void*)cubtmp, tmp2, keys, keysB, vals, valsB, EDG_, 0, SORT_BITS);
}

extern "C" void kernel_launch(void* const* d_in, const int* in_sizes, int n_in,
                              void* d_out, int out_size) {
    const float* x    = (const float*)d_in[0];
    const int*   ei   = (const int*)d_in[1];
    const int*   src  = ei;
    const int*   dst  = ei + EDG_;
    const float* W0   = (const float*)d_in[3];
    const float* b0   = (const float*)d_in[4];
    const float* W1a  = (const float*)d_in[5];
    const float* b1a  = (const float*)d_in[6];
    const float* W1b  = (const float*)d_in[7];
    const float* b1b  = (const float*)d_in[8];
    const float* Wrel1  = (const float*)d_in[9];
    const float* brel1  = (const float*)d_in[10];
    const float* Wroot1 = (const float*)d_in[11];
    const float* W2a  = (const float*)d_in[12];
    const float* b2a  = (const float*)d_in[13];
    const float* W2b  = (const float*)d_in[14];
    const float* b2b  = (const float*)d_in[15];
    const float* Wrel2  = (const float*)d_in[16];
    const float* brel2  = (const float*)d_in[17];
    const float* Wroot2 = (const float*)d_in[18];
    const float* Wg   = (const float*)d_in[19];
    const float* bg   = (const float*)d_in[20];
    const float* Wr1  = (const float*)d_in[21];
    const float* br1  = (const float*)d_in[22];
    const float* gg1  = (const float*)d_in[23];
    const float* be1  = (const float*)d_in[24];
    const float* Wr2  = (const float*)d_in[25];
    const float* br2  = (const float*)d_in[26];
    const float* gg2  = (const float*)d_in[27];
    const float* be2  = (const float*)d_in[28];
    const float* Wout = (const float*)d_in[29];

    float *bufA, *bufB, *bufC, *scores, *skey, *srel, *sroot, *o1, *o2;
    int *iota, *sidx, *newid, *src2, *dst2, *offs;
    int *keys, *keysB, *vals, *valsB, *counts, *rowptr;
    unsigned char *mask2, *cubtmp;
    cudaGetSymbolAddress((void**)&bufA, g_bufA);
    cudaGetSymbolAddress((void**)&bufB, g_bufB);
    cudaGetSymbolAddress((void**)&bufC, g_bufC);
    cudaGetSymbolAddress((void**)&scores, g_scores);
    cudaGetSymbolAddress((void**)&skey, g_skey);
    cudaGetSymbolAddress((void**)&srel, g_srel);
    cudaGetSymbolAddress((void**)&sroot, g_sroot);
    cudaGetSymbolAddress((void**)&iota, g_iota);
    cudaGetSymbolAddress((void**)&sidx, g_sidx);
    cudaGetSymbolAddress((void**)&newid, g_newid);
    cudaGetSymbolAddress((void**)&src2, g_src2);
    cudaGetSymbolAddress((void**)&dst2, g_dst2);
    cudaGetSymbolAddress((void**)&mask2, g_mask2);
    cudaGetSymbolAddress((void**)&offs, g_offs);
    cudaGetSymbolAddress((void**)&o1, g_out1);
    cudaGetSymbolAddress((void**)&o2, g_out2);
    cudaGetSymbolAddress((void**)&keys, g_keys);
    cudaGetSymbolAddress((void**)&keysB, g_keysB);
    cudaGetSymbolAddress((void**)&vals, g_vals);
    cudaGetSymbolAddress((void**)&valsB, g_valsB);
    cudaGetSymbolAddress((void**)&counts, g_counts);
    cudaGetSymbolAddress((void**)&rowptr, g_rowptr);
    cudaGetSymbolAddress((void**)&cubtmp, g_cubtmp);

    // ---- layer-1 CSR (all edges valid), deterministic edge order
    build_csr(dst, src, nullptr, keys, keysB, vals, valsB, counts, rowptr, cubtmp, NB_);

    // ---- stage 0: h0 = relu(x @ W0 + b0) -> bufA
    gemm_kernel<FF_, true><<<NB_ / 128, 256>>>(x, W0, b0, bufA);

    // ---- GIN layer 1: t = h0 + segsum(h0[src] -> dst) ; h1 = nn(t)
    agg_kernel<true><<<NB_ / 8, 256>>>(bufA, rowptr, valsB, bufB, NB_);
    gemm_kernel<CC_, true ><<<NB_ / 128, 256>>>(bufB, W1a, b1a, bufC);
    gemm_kernel<CC_, false><<<NB_ / 128, 256>>>(bufC, W1b, b1b, bufB);  // h1 = bufB

    // ---- SAGPool 1 (linearity: aggregate scalar h.Wrel instead of vectors)
    score_pre_kernel<<<(NB_ + 255) / 256, 256>>>(bufB, Wrel1, Wroot1, srel, sroot, NB_);
    score_agg_kernel<<<(NB_ + 255) / 256, 256>>>(srel, sroot, brel1, rowptr, valsB, scores, NB_);
    iota_kernel<<<(NB_ + 255) / 256, 256>>>(iota, NB_);
    offs_kernel<<<1, 32>>>(offs, NPG_);
    {
        size_t tmp = 0;
        cub::DeviceSegmentedRadixSort::SortPairsDescending(
            nullptr, tmp, scores, skey, iota, sidx, NB_, BGR_, offs, offs + 1);
        if (tmp > sizeof(g_cubtmp)) tmp = sizeof(g_cubtmp);
        cub::DeviceSegmentedRadixSort::SortPairsDescending(
            (void*)cubtmp, tmp, scores, skey, iota, sidx, NB_, BGR_, offs, offs + 1);
    }
    filln1_kernel<<<(NB_ + 255) / 256, 256>>>(newid, NB_);
    select_kernel<<<NB1_ / 8, 256>>>(skey, sidx, bufB, bufC, newid, NPG_, KK1_);  // h2 = bufC
    mean_kernel<<<BGR_, 256>>>(bufC, o1, KK1_);
    remap_kernel<<<EDG_ / 256, 256>>>(src, dst, newid, src2, dst2, mask2);

    // ---- layer-2 CSR (masked edges excluded), deterministic edge order
    build_csr(dst2, src2, mask2, keys, keysB, vals, valsB, counts, rowptr, cubtmp, NB1_);

    // ---- GIN layer 2
    agg_kernel<true><<<NB1_ / 8, 256>>>(bufC, rowptr, valsB, bufA, NB1_);
    gemm_kernel<CC_, true ><<<NB1_ / 128, 256>>>(bufA, W2a, b2a, bufB);
    gemm_kernel<CC_, false><<<NB1_ / 128, 256>>>(bufB, W2b, b2b, bufC);  // h3 = bufC

    // ---- SAGPool 2
    score_pre_kernel<<<(NB1_ + 255) / 256, 256>>>(bufC, Wrel2, Wroot2, srel, sroot, NB1_);
    score_agg_kernel<<<(NB1_ + 255) / 256, 256>>>(srel, sroot, brel2, rowptr, valsB, scores, NB1_);
    iota_kernel<<<(NB1_ + 255) / 256, 256>>>(iota, NB1_);
    offs_kernel<<<1, 32>>>(offs, KK1_);
    {
        size_t tmp = 0;
        cub::DeviceSegmentedRadixSort::SortPairsDescending(
            nullptr, tmp, scores, skey, iota, sidx, NB1_, BGR_, offs, offs + 1);
        if (tmp > sizeof(g_cubtmp)) tmp = sizeof(g_cubtmp);
        cub::DeviceSegmentedRadixSort::SortPairsDescending(
            (void*)cubtmp, tmp, scores, skey, iota, sidx, NB1_, BGR_, offs, offs + 1);
    }
    select_kernel<<<NB2_ / 8, 256>>>(skey, sidx, bufC, bufB, newid, KK1_, KK2_);  // h4 = bufB
    mean_kernel<<<BGR_, 256>>>(bufB, o2, KK2_);

    // ---- head
    head_kernel<<<1, 256>>>(o1, o2, Wg, bg, Wr1, br1, gg1, be1,
                            Wr2, br2, gg2, be2, Wout, (float*)d_out);
}

// round 7
// speedup vs baseline: 1.1329x; 1.1262x over previous
#include <cuda_runtime.h>
#include <cub/cub.cuh>

// Problem constants
#define NB_   80000      // B*N nodes layer 0/1
#define BGR_  8          // graphs
#define NPG_  10000      // nodes per graph (layer 1)
#define EDG_  640000     // edges
#define CC_   128        // channels
#define FF_   64         // input features
#define KK1_  6000       // kept after pool1 (per graph)
#define NB1_  48000      // B*KK1
#define KK2_  3600       // kept after pool2 (per graph)
#define NB2_  28800      // B*KK2

// ---------------- static device scratch (no allocs allowed) ----------------
__device__ float g_bufA[NB_ * CC_];
__device__ float g_bufB[NB_ * CC_];
__device__ float g_bufC[NB_ * CC_];
__device__ float g_scores[NB_];
__device__ float g_skey[NB_];
__device__ float g_srel[NB_];
__device__ float g_sroot[NB_];
__device__ float g_ssum[NB_];
__device__ int   g_iota[NB_];
__device__ int   g_sidx[NB_];
__device__ int   g_newid[NB_];
__device__ int   g_src2[EDG_];
__device__ int   g_dst2[EDG_];
__device__ unsigned char g_mask2[EDG_];
__device__ int   g_offs[9];
__device__ float g_out1[BGR_ * CC_];
__device__ float g_out2[BGR_ * CC_];
__device__ unsigned char g_cubtmp[1u << 24];  // 16 MB cub temp (segmented sorts)

// ---------------- XLA-GPU (MLIR math polynomial approximation) tanh -------
__device__ __forceinline__ float xla_tanh(float ax) {
    const float plus_clamp  = 7.99881172180175781f;
    const float minus_clamp = -7.99881172180175781f;
    const float tiny = 0.0004f;
    const float alpha_1  = 4.89352455891786e-03f;
    const float alpha_3  = 6.37261928875436e-04f;
    const float alpha_5  = 1.48572235717979e-05f;
    const float alpha_7  = 5.12229709037114e-08f;
    const float alpha_9  = -8.60467152213735e-11f;
    const float alpha_11 = 2.00018790482477e-13f;
    const float alpha_13 = -2.76076847742355e-16f;
    const float beta_0 = 4.89352518554385e-03f;
    const float beta_2 = 2.26843463243900e-03f;
    const float beta_4 = 1.18534705686654e-04f;
    const float beta_6 = 1.19825839466702e-06f;

    float x = fminf(fmaxf(ax, minus_clamp), plus_clamp);
    float x2 = x * x;
    float p = fmaf(x2, alpha_13, alpha_11);
    p = fmaf(x2, p, alpha_9);
    p = fmaf(x2, p, alpha_7);
    p = fmaf(x2, p, alpha_5);
    p = fmaf(x2, p, alpha_3);
    p = fmaf(x2, p, alpha_1);
    p = x * p;
    float q = fmaf(x2, beta_6, beta_4);
    q = fmaf(x2, q, beta_2);
    q = fmaf(x2, q, beta_0);
    float r = p / q;
    return (fabsf(ax) < tiny) ? ax : r;
}

// ---------------- GEMM: [M x K] @ [K x 128] + bias (+relu) ----------------
// R4-proven 64x128 tile, 256 threads, 8x4 microtile, k-sequential FMA.
template <int K, bool RELU>
__global__ void __launch_bounds__(256) gemm_kernel(const float* __restrict__ A,
                                                   const float* __restrict__ W,
                                                   const float* __restrict__ bias,
                                                   float* __restrict__ out) {
    __shared__ float As[64][36];
    __shared__ float Bs[32][128];

    const int tid  = threadIdx.x;
    const int row0 = blockIdx.x * 64;
    const int warp = tid >> 5, lane = tid & 31;
    const int r0 = warp * 8;
    const int c0 = lane * 4;

    float acc[8][4];
#pragma unroll
    for (int i = 0; i < 8; i++)
#pragma unroll
        for (int j = 0; j < 4; j++) acc[i][j] = 0.f;

    for (int k0 = 0; k0 < K; k0 += 32) {
        {
            const int r  = tid >> 3;
            const int k4 = (tid & 7) * 4;
            float4 v0 = *(const float4*)(A + (size_t)(row0 + r) * K + k0 + k4);
            float4 v1 = *(const float4*)(A + (size_t)(row0 + r + 32) * K + k0 + k4);
            *(float4*)&As[r][k4]      = v0;
            *(float4*)&As[r + 32][k4] = v1;
        }
#pragma unroll
        for (int it = 0; it < 4; ++it) {
            const int f  = tid + it * 256;
            const int k  = f >> 5;
            const int c4 = (f & 31) * 4;
            *(float4*)&Bs[k][c4] = *(const float4*)(W + (size_t)(k0 + k) * 128 + c4);
        }
        __syncthreads();
#pragma unroll
        for (int kk = 0; kk < 32; ++kk) {
            const float4 b = *(const float4*)&Bs[kk][c0];
#pragma unroll
            for (int i = 0; i < 8; i++) {
                const float a = As[r0 + i][kk];
                acc[i][0] = fmaf(a, b.x, acc[i][0]);
                acc[i][1] = fmaf(a, b.y, acc[i][1]);
                acc[i][2] = fmaf(a, b.z, acc[i][2]);
                acc[i][3] = fmaf(a, b.w, acc[i][3]);
            }
        }
        __syncthreads();
    }

    const float4 bv = *(const float4*)(bias + c0);
#pragma unroll
    for (int i = 0; i < 8; i++) {
        float4 o;
        o.x = acc[i][0] + bv.x;
        o.y = acc[i][1] + bv.y;
        o.z = acc[i][2] + bv.z;
        o.w = acc[i][3] + bv.w;
        if (RELU) {
            o.x = fmaxf(o.x, 0.f); o.y = fmaxf(o.y, 0.f);
            o.z = fmaxf(o.z, 0.f); o.w = fmaxf(o.w, 0.f);
        }
        *(float4*)(out + (size_t)(row0 + r0 + i) * 128 + c0) = o;
    }
}

// ---------------- edge vector scatter-add (1 warp / edge) -----------------
__global__ void scatter_kernel(const float* __restrict__ x, const int* __restrict__ src,
                               const int* __restrict__ dst,
                               const unsigned char* __restrict__ mask,
                               float* __restrict__ agg, int nE) {
    const int e = blockIdx.x * 8 + (threadIdx.x >> 5);
    if (e >= nE) return;
    if (mask && !mask[e]) return;
    const int lane = threadIdx.x & 31;
    const int s = src[e], d = dst[e];
    float4 v = *(const float4*)(x + (size_t)s * CC_ + lane * 4);
    atomicAdd((float4*)(agg + (size_t)d * CC_ + lane * 4), v);  // sm_90+ vector RED
}

// ---------------- scalar edge scatter-add for scores ----------------------
__global__ void scatter_scalar_kernel(const float* __restrict__ srel,
                                      const int* __restrict__ src,
                                      const int* __restrict__ dst,
                                      const unsigned char* __restrict__ mask,
                                      float* __restrict__ ssum, int nE) {
    const int e = blockIdx.x * blockDim.x + threadIdx.x;
    if (e >= nE) return;
    if (mask && !mask[e]) return;
    atomicAdd(&ssum[dst[e]], srel[src[e]]);
}

// ---------------- score pre-pass: srel = h.Wrel, sroot = h.Wroot ----------
__global__ void score_pre_kernel(const float* __restrict__ x,
                                 const float* __restrict__ Wrel,
                                 const float* __restrict__ Wroot,
                                 float* __restrict__ srel, float* __restrict__ sroot,
                                 int n) {
    const int node = blockIdx.x * blockDim.x + threadIdx.x;
    if (node >= n) return;
    const float* xx = x + (size_t)node * CC_;
    float t1 = 0.f, t2 = 0.f;
#pragma unroll 16
    for (int c = 0; c < CC_; ++c) t1 = fmaf(xx[c], Wrel[c], t1);
#pragma unroll 16
    for (int c = 0; c < CC_; ++c) t2 = fmaf(xx[c], Wroot[c], t2);
    srel[node] = t1;
    sroot[node] = t2;
}

// ---------------- score finalize: tanh((ssum+brel)+sroot) -----------------
__global__ void score_fin_kernel(const float* __restrict__ ssum,
                                 const float* __restrict__ sroot,
                                 const float* __restrict__ brel,
                                 float* __restrict__ scores, int n) {
    const int node = blockIdx.x * blockDim.x + threadIdx.x;
    if (node >= n) return;
    scores[node] = xla_tanh((ssum[node] + brel[0]) + sroot[node]);
}

// ---------------- small helpers ----------------
__global__ void iota_kernel(int* a, int n) {
    int i = blockIdx.x * blockDim.x + threadIdx.x;
    if (i < n) a[i] = i;
}
__global__ void filln1_kernel(int* a, int n) {
    int i = blockIdx.x * blockDim.x + threadIdx.x;
    if (i < n) a[i] = -1;
}
__global__ void zerof_kernel(float* a, int n) {
    int i = blockIdx.x * blockDim.x + threadIdx.x;
    if (i < n) a[i] = 0.f;
}
__global__ void copy4_kernel(const float4* __restrict__ in, float4* __restrict__ out, int n4) {
    for (int i = blockIdx.x * blockDim.x + threadIdx.x; i < n4; i += gridDim.x * blockDim.x)
        out[i] = in[i];
}
__global__ void offs_kernel(int* offs, int npg) {
    int t = threadIdx.x;
    if (t < 9) offs[t] = t * npg;
}

// ---------------- selection/gather after sort (1 warp / kept node) -------
__global__ void select_kernel(const float* __restrict__ skey, const int* __restrict__ sidx,
                              const float* __restrict__ xin, float* __restrict__ xout,
                              int* __restrict__ newid, int npg, int k) {
    const int j = blockIdx.x * 8 + (threadIdx.x >> 5);
    if (j >= BGR_ * k) return;
    const int g = j / k, jj = j - g * k;
    const int srcpos = g * npg + jj;
    const int orig = sidx[srcpos];
    const float val = skey[srcpos];
    const int lane = threadIdx.x & 31;
    float4 v = *(const float4*)(xin + (size_t)orig * CC_ + lane * 4);
    v.x *= val; v.y *= val; v.z *= val; v.w *= val;
    *(float4*)(xout + (size_t)j * CC_ + lane * 4) = v;
    if (lane == 0) newid[orig] = j;
}

// ---------------- edge remap after pooling ----------------
__global__ void remap_kernel(const int* __restrict__ src, const int* __restrict__ dst,
                             const int* __restrict__ newid,
                             int* __restrict__ src2, int* __restrict__ dst2,
                             unsigned char* __restrict__ mask2) {
    const int e = blockIdx.x * blockDim.x + threadIdx.x;
    if (e >= EDG_) return;
    const int s = newid[src[e]];
    const int d = newid[dst[e]];
    const bool ok = (s >= 0) && (d >= 0);
    src2[e] = s; dst2[e] = d; mask2[e] = ok ? 1 : 0;
}

// ---------------- per-graph mean pooling ----------------
__global__ void mean_kernel(const float* __restrict__ x, float* __restrict__ out, int k) {
    __shared__ float col[CC_];
    const int b = blockIdx.x, tid = threadIdx.x;
    if (tid < CC_) col[tid] = 0.f;
    __syncthreads();
    float s = 0.f;
    const float* base = x + (size_t)b * k * CC_;
    const int total = k * CC_;
    for (int idx = tid; idx < total; idx += 256) s += base[idx];
    atomicAdd(&col[tid & 127], s);
    __syncthreads();
    if (tid < CC_) out[b * CC_ + tid] = col[tid] / (float)k;
}

// ---------------- final MLP head (single block) ----------------
__global__ void head_kernel(const float* __restrict__ out1, const float* __restrict__ out2,
                            const float* __restrict__ Wg, const float* __restrict__ bg,
                            const float* __restrict__ Wr1, const float* __restrict__ br1,
                            const float* __restrict__ gg1, const float* __restrict__ be1,
                            const float* __restrict__ Wr2, const float* __restrict__ br2,
                            const float* __restrict__ gg2, const float* __restrict__ be2,
                            const float* __restrict__ Wout, float* __restrict__ out) {
    __shared__ float cat[8][256];
    __shared__ float gmat[8][128];
    __shared__ float r1[8][64];
    __shared__ float r2[8][32];
    const int tid = threadIdx.x;  // 256 threads
    for (int i = tid; i < 8 * 128; i += 256) {
        const int b = i >> 7, c = i & 127;
        cat[b][c]       = out1[i];
        cat[b][c + 128] = out2[i];
    }
    __syncthreads();
    const float inv = 1.0f / sqrtf(1.0f + 1e-5f);
    if (tid < 128) {
        for (int b = 0; b < 8; b++) {
            float s = 0.f;
            for (int k = 0; k < 256; k++) s = fmaf(cat[b][k], Wg[k * 128 + tid], s);
            gmat[b][tid] = s + bg[tid];
        }
    }
    __syncthreads();
    if (tid < 64) {
        for (int b = 0; b < 8; b++) {
            float s = 0.f;
            for (int k = 0; k < 128; k++) s = fmaf(gmat[b][k], Wr1[k * 64 + tid], s);
            s = (s + br1[tid]) * inv * gg1[tid] + be1[tid];
            r1[b][tid] = fmaxf(s, 0.f);
        }
    }
    __syncthreads();
    if (tid < 32) {
        for (int b = 0; b < 8; b++) {
            float s = 0.f;
            for (int k = 0; k < 64; k++) s = fmaf(r1[b][k], Wr2[k * 32 + tid], s);
            s = (s + br2[tid]) * inv * gg2[tid] + be2[tid];
            r2[b][tid] = fmaxf(s, 0.f);
        }
    }
    __syncthreads();
    if (tid < 32) {
        const int b = tid >> 2, j = tid & 3;
        float s = 0.f;
        for (int k = 0; k < 32; k++) s = fmaf(r2[b][k], Wout[k * 4 + j], s);
        out[b * 4 + j] = s;
    }
}

// ---------------- host orchestration ----------------
extern "C" void kernel_launch(void* const* d_in, const int* in_sizes, int n_in,
                              void* d_out, int out_size) {
    const float* x    = (const float*)d_in[0];
    const int*   ei   = (const int*)d_in[1];
    const int*   src  = ei;
    const int*   dst  = ei + EDG_;
    const float* W0   = (const float*)d_in[3];
    const float* b0   = (const float*)d_in[4];
    const float* W1a  = (const float*)d_in[5];
    const float* b1a  = (const float*)d_in[6];
    const float* W1b  = (const float*)d_in[7];
    const float* b1b  = (const float*)d_in[8];
    const float* Wrel1  = (const float*)d_in[9];
    const float* brel1  = (const float*)d_in[10];
    const float* Wroot1 = (const float*)d_in[11];
    const float* W2a  = (const float*)d_in[12];
    const float* b2a  = (const float*)d_in[13];
    const float* W2b  = (const float*)d_in[14];
    const float* b2b  = (const float*)d_in[15];
    const float* Wrel2  = (const float*)d_in[16];
    const float* brel2  = (const float*)d_in[17];
    const float* Wroot2 = (const float*)d_in[18];
    const float* Wg   = (const float*)d_in[19];
    const float* bg   = (const float*)d_in[20];
    const float* Wr1  = (const float*)d_in[21];
    const float* br1  = (const float*)d_in[22];
    const float* gg1  = (const float*)d_in[23];
    const float* be1  = (const float*)d_in[24];
    const float* Wr2  = (const float*)d_in[25];
    const float* br2  = (const float*)d_in[26];
    const float* gg2  = (const float*)d_in[27];
    const float* be2  = (const float*)d_in[28];
    const float* Wout = (const float*)d_in[29];

    float *bufA, *bufB, *bufC, *scores, *skey, *srel, *sroot, *ssum, *o1, *o2;
    int *iota, *sidx, *newid, *src2, *dst2, *offs;
    unsigned char *mask2, *cubtmp;
    cudaGetSymbolAddress((void**)&bufA, g_bufA);
    cudaGetSymbolAddress((void**)&bufB, g_bufB);
    cudaGetSymbolAddress((void**)&bufC, g_bufC);
    cudaGetSymbolAddress((void**)&scores, g_scores);
    cudaGetSymbolAddress((void**)&skey, g_skey);
    cudaGetSymbolAddress((void**)&srel, g_srel);
    cudaGetSymbolAddress((void**)&sroot, g_sroot);
    cudaGetSymbolAddress((void**)&ssum, g_ssum);
    cudaGetSymbolAddress((void**)&iota, g_iota);
    cudaGetSymbolAddress((void**)&sidx, g_sidx);
    cudaGetSymbolAddress((void**)&newid, g_newid);
    cudaGetSymbolAddress((void**)&src2, g_src2);
    cudaGetSymbolAddress((void**)&dst2, g_dst2);
    cudaGetSymbolAddress((void**)&mask2, g_mask2);
    cudaGetSymbolAddress((void**)&offs, g_offs);
    cudaGetSymbolAddress((void**)&o1, g_out1);
    cudaGetSymbolAddress((void**)&o2, g_out2);
    cudaGetSymbolAddress((void**)&cubtmp, g_cubtmp);

    const int n4_full = NB_ * CC_ / 4;
    const int n4_l2   = NB1_ * CC_ / 4;

    // ---- stage 0: h0 = relu(x @ W0 + b0) -> bufA
    gemm_kernel<FF_, true><<<NB_ / 64, 256>>>(x, W0, b0, bufA);

    // ---- GIN layer 1: t = h0 + segsum(h0[src] -> dst) ; h1 = nn(t)
    copy4_kernel<<<4096, 256>>>((const float4*)bufA, (float4*)bufB, n4_full);
    scatter_kernel<<<EDG_ / 8, 256>>>(bufA, src, dst, nullptr, bufB, EDG_);
    gemm_kernel<CC_, true ><<<NB_ / 64, 256>>>(bufB, W1a, b1a, bufC);
    gemm_kernel<CC_, false><<<NB_ / 64, 256>>>(bufC, W1b, b1b, bufB);  // h1 = bufB

    // ---- SAGPool 1 (linearity: aggregate scalar h.Wrel)
    score_pre_kernel<<<(NB_ + 255) / 256, 256>>>(bufB, Wrel1, Wroot1, srel, sroot, NB_);
    zerof_kernel<<<(NB_ + 255) / 256, 256>>>(ssum, NB_);
    scatter_scalar_kernel<<<(EDG_ + 255) / 256, 256>>>(srel, src, dst, nullptr, ssum, EDG_);
    score_fin_kernel<<<(NB_ + 255) / 256, 256>>>(ssum, sroot, brel1, scores, NB_);
    iota_kernel<<<(NB_ + 255) / 256, 256>>>(iota, NB_);
    offs_kernel<<<1, 32>>>(offs, NPG_);
    {
        size_t tmp = 0;
        cub::DeviceSegmentedRadixSort::SortPairsDescending(
            nullptr, tmp, scores, skey, iota, sidx, NB_, BGR_, offs, offs + 1);
        if (tmp > sizeof(g_cubtmp)) tmp = sizeof(g_cubtmp);
        cub::DeviceSegmentedRadixSort::SortPairsDescending(
            (void*)cubtmp, tmp, scores, skey, iota, sidx, NB_, BGR_, offs, offs + 1);
    }
    filln1_kernel<<<(NB_ + 255) / 256, 256>>>(newid, NB_);
    select_kernel<<<NB1_ / 8, 256>>>(skey, sidx, bufB, bufC, newid, NPG_, KK1_);  // h2 = bufC
    mean_kernel<<<BGR_, 256>>>(bufC, o1, KK1_);
    remap_kernel<<<EDG_ / 256, 256>>>(src, dst, newid, src2, dst2, mask2);

    // ---- GIN layer 2
    copy4_kernel<<<4096, 256>>>((const float4*)bufC, (float4*)bufA, n4_l2);
    scatter_kernel<<<EDG_ / 8, 256>>>(bufC, src2, dst2, mask2, bufA, EDG_);
    gemm_kernel<CC_, true ><<<NB1_ / 64, 256>>>(bufA, W2a, b2a, bufB);
    gemm_kernel<CC_, false><<<NB1_ / 64, 256>>>(bufB, W2b, b2b, bufC);  // h3 = bufC

    // ---- SAGPool 2
    score_pre_kernel<<<(NB1_ + 255) / 256, 256>>>(bufC, Wrel2, Wroot2, srel, sroot, NB1_);
    zerof_kernel<<<(NB1_ + 255) / 256, 256>>>(ssum, NB1_);
    scatter_scalar_kernel<<<(EDG_ + 255) / 256, 256>>>(srel, src2, dst2, mask2, ssum, EDG_);
    score_fin_kernel<<<(NB1_ + 255) / 256, 256>>>(ssum, sroot, brel2, scores, NB1_);
    iota_kernel<<<(NB1_ + 255) / 256, 256>>>(iota, NB1_);
    offs_kernel<<<1, 32>>>(offs, KK1_);
    {
        size_t tmp = 0;
        cub::DeviceSegmentedRadixSort::SortPairsDescending(
            nullptr, tmp, scores, skey, iota, sidx, NB1_, BGR_, offs, offs + 1);
        if (tmp > sizeof(g_cubtmp)) tmp = sizeof(g_cubtmp);
        cub::DeviceSegmentedRadixSort::SortPairsDescending(
            (void*)cubtmp, tmp, scores, skey, iota, sidx, NB1_, BGR_, offs, offs + 1);
    }
    select_kernel<<<NB2_ / 8, 256>>>(skey, sidx, bufC, bufB, newid, KK1_, KK2_);  // h4 = bufB
    mean_kernel<<<BGR_, 256>>>(bufB, o2, KK2_);

    // ---- head
    head_kernel<<<1, 256>>>(o1, o2, Wg, bg, Wr1, br1, gg1, be1,
                            Wr2, br2, gg2, be2, Wout, (float*)d_out);
}

// round 8
// speedup vs baseline: 1.3601x; 1.2005x over previous
#include <cuda_runtime.h>
#include <cub/cub.cuh>

// Problem constants
#define NB_   80000      // B*N nodes layer 0/1
#define BGR_  8          // graphs
#define NPG_  10000      // nodes per graph (layer 1)
#define EDG_  640000     // edges
#define CC_   128        // channels
#define FF_   64         // input features
#define KK1_  6000       // kept after pool1 (per graph)
#define NB1_  48000      // B*KK1
#define KK2_  3600       // kept after pool2 (per graph)
#define NB2_  28800      // B*KK2

// ---------------- static device scratch (no allocs allowed) ----------------
__device__ float g_bufA[NB_ * CC_];
__device__ float g_bufB[NB_ * CC_];
__device__ float g_bufC[NB_ * CC_];
__device__ float g_scores[NB_];
__device__ float g_srel[NB_];
__device__ float g_sroot[NB_];
__device__ float g_ssum[NB_];
__device__ unsigned long long g_key64[NB_];
__device__ unsigned long long g_key64B[NB_];
__device__ int   g_iota[NB_];
__device__ int   g_sidx[NB_];
__device__ int   g_newid[NB_];
__device__ int   g_src2[EDG_];
__device__ int   g_dst2[EDG_];
__device__ unsigned char g_mask2[EDG_];
__device__ float g_out1[BGR_ * CC_];
__device__ float g_out2[BGR_ * CC_];
__device__ unsigned char g_cubtmp[1u << 24];  // 16 MB cub temp

// ---------------- XLA-GPU (MLIR math polynomial approximation) tanh -------
__device__ __forceinline__ float xla_tanh(float ax) {
    const float plus_clamp  = 7.99881172180175781f;
    const float minus_clamp = -7.99881172180175781f;
    const float tiny = 0.0004f;
    const float alpha_1  = 4.89352455891786e-03f;
    const float alpha_3  = 6.37261928875436e-04f;
    const float alpha_5  = 1.48572235717979e-05f;
    const float alpha_7  = 5.12229709037114e-08f;
    const float alpha_9  = -8.60467152213735e-11f;
    const float alpha_11 = 2.00018790482477e-13f;
    const float alpha_13 = -2.76076847742355e-16f;
    const float beta_0 = 4.89352518554385e-03f;
    const float beta_2 = 2.26843463243900e-03f;
    const float beta_4 = 1.18534705686654e-04f;
    const float beta_6 = 1.19825839466702e-06f;

    float x = fminf(fmaxf(ax, minus_clamp), plus_clamp);
    float x2 = x * x;
    float p = fmaf(x2, alpha_13, alpha_11);
    p = fmaf(x2, p, alpha_9);
    p = fmaf(x2, p, alpha_7);
    p = fmaf(x2, p, alpha_5);
    p = fmaf(x2, p, alpha_3);
    p = fmaf(x2, p, alpha_1);
    p = x * p;
    float q = fmaf(x2, beta_6, beta_4);
    q = fmaf(x2, q, beta_2);
    q = fmaf(x2, q, beta_0);
    float r = p / q;
    return (fabsf(ax) < tiny) ? ax : r;
}

// ---------------- GEMM: [M x K] @ [K x 128] + bias (+relu) ----------------
template <int K, bool RELU>
__global__ void __launch_bounds__(256) gemm_kernel(const float* __restrict__ A,
                                                   const float* __restrict__ W,
                                                   const float* __restrict__ bias,
                                                   float* __restrict__ out) {
    __shared__ float As[64][36];
    __shared__ float Bs[32][128];

    const int tid  = threadIdx.x;
    const int row0 = blockIdx.x * 64;
    const int warp = tid >> 5, lane = tid & 31;
    const int r0 = warp * 8;
    const int c0 = lane * 4;

    float acc[8][4];
#pragma unroll
    for (int i = 0; i < 8; i++)
#pragma unroll
        for (int j = 0; j < 4; j++) acc[i][j] = 0.f;

    for (int k0 = 0; k0 < K; k0 += 32) {
        {
            const int r  = tid >> 3;
            const int k4 = (tid & 7) * 4;
            float4 v0 = *(const float4*)(A + (size_t)(row0 + r) * K + k0 + k4);
            float4 v1 = *(const float4*)(A + (size_t)(row0 + r + 32) * K + k0 + k4);
            *(float4*)&As[r][k4]      = v0;
            *(float4*)&As[r + 32][k4] = v1;
        }
#pragma unroll
        for (int it = 0; it < 4; ++it) {
            const int f  = tid + it * 256;
            const int k  = f >> 5;
            const int c4 = (f & 31) * 4;
            *(float4*)&Bs[k][c4] = *(const float4*)(W + (size_t)(k0 + k) * 128 + c4);
        }
        __syncthreads();
#pragma unroll
        for (int kk = 0; kk < 32; ++kk) {
            const float4 b = *(const float4*)&Bs[kk][c0];
#pragma unroll
            for (int i = 0; i < 8; i++) {
                const float a = As[r0 + i][kk];
                acc[i][0] = fmaf(a, b.x, acc[i][0]);
                acc[i][1] = fmaf(a, b.y, acc[i][1]);
                acc[i][2] = fmaf(a, b.z, acc[i][2]);
                acc[i][3] = fmaf(a, b.w, acc[i][3]);
            }
        }
        __syncthreads();
    }

    const float4 bv = *(const float4*)(bias + c0);
#pragma unroll
    for (int i = 0; i < 8; i++) {
        float4 o;
        o.x = acc[i][0] + bv.x;
        o.y = acc[i][1] + bv.y;
        o.z = acc[i][2] + bv.z;
        o.w = acc[i][3] + bv.w;
        if (RELU) {
            o.x = fmaxf(o.x, 0.f); o.y = fmaxf(o.y, 0.f);
            o.z = fmaxf(o.z, 0.f); o.w = fmaxf(o.w, 0.f);
        }
        *(float4*)(out + (size_t)(row0 + r0 + i) * 128 + c0) = o;
    }
}

// ---------------- edge vector scatter-add (1 warp / edge) -----------------
__global__ void scatter_kernel(const float* __restrict__ x, const int* __restrict__ src,
                               const int* __restrict__ dst,
                               const unsigned char* __restrict__ mask,
                               float* __restrict__ agg, int nE) {
    const int e = blockIdx.x * 8 + (threadIdx.x >> 5);
    if (e >= nE) return;
    if (mask && !mask[e]) return;
    const int lane = threadIdx.x & 31;
    const int s = src[e], d = dst[e];
    float4 v = *(const float4*)(x + (size_t)s * CC_ + lane * 4);
    atomicAdd((float4*)(agg + (size_t)d * CC_ + lane * 4), v);  // sm_90+ vector RED
}

// ---------------- scalar edge scatter-add for scores ----------------------
__global__ void scatter_scalar_kernel(const float* __restrict__ srel,
                                      const int* __restrict__ src,
                                      const int* __restrict__ dst,
                                      const unsigned char* __restrict__ mask,
                                      float* __restrict__ ssum, int nE) {
    const int e = blockIdx.x * blockDim.x + threadIdx.x;
    if (e >= nE) return;
    if (mask && !mask[e]) return;
    atomicAdd(&ssum[dst[e]], srel[src[e]]);
}

// ---------------- score pre-pass: srel = h.Wrel, sroot = h.Wroot ----------
__global__ void score_pre_kernel(const float* __restrict__ x,
                                 const float* __restrict__ Wrel,
                                 const float* __restrict__ Wroot,
                                 float* __restrict__ srel, float* __restrict__ sroot,
                                 int n) {
    const int node = blockIdx.x * blockDim.x + threadIdx.x;
    if (node >= n) return;
    const float* xx = x + (size_t)node * CC_;
    float t1 = 0.f, t2 = 0.f;
#pragma unroll 16
    for (int c = 0; c < CC_; ++c) t1 = fmaf(xx[c], Wrel[c], t1);
#pragma unroll 16
    for (int c = 0; c < CC_; ++c) t2 = fmaf(xx[c], Wroot[c], t2);
    srel[node] = t1;
    sroot[node] = t2;
}

// ---------------- score finalize + composite sort key ---------------------
// key64 = (graph_id << 32) | desc_encode(score): stable ascending radix sort
// == per-graph descending-score order with ascending-index tie-break.
__global__ void score_fin_kernel(const float* __restrict__ ssum,
                                 const float* __restrict__ sroot,
                                 const float* __restrict__ brel,
                                 float* __restrict__ scores,
                                 unsigned long long* __restrict__ key64,
                                 int* __restrict__ iota, int npg, int n) {
    const int node = blockIdx.x * blockDim.x + threadIdx.x;
    if (node >= n) return;
    const float sc = xla_tanh((ssum[node] + brel[0]) + sroot[node]);
    scores[node] = sc;
    unsigned int u = __float_as_uint(sc);
    unsigned int e = (u & 0x80000000u) ? ~u : (u | 0x80000000u); // ascending encode
    unsigned int kd = ~e;                                         // descending
    const unsigned int g = (unsigned int)(node / npg);
    key64[node] = ((unsigned long long)g << 32) | (unsigned long long)kd;
    iota[node] = node;
}

// ---------------- small helpers ----------------
__global__ void filln1_kernel(int* a, int n) {
    int i = blockIdx.x * blockDim.x + threadIdx.x;
    if (i < n) a[i] = -1;
}
__global__ void zerof_kernel(float* a, int n) {
    int i = blockIdx.x * blockDim.x + threadIdx.x;
    if (i < n) a[i] = 0.f;
}
__global__ void copy4_kernel(const float4* __restrict__ in, float4* __restrict__ out, int n4) {
    for (int i = blockIdx.x * blockDim.x + threadIdx.x; i < n4; i += gridDim.x * blockDim.x)
        out[i] = in[i];
}

// ---------------- selection/gather after sort (1 warp / kept node) -------
__global__ void select_kernel(const float* __restrict__ scores, const int* __restrict__ sidx,
                              const float* __restrict__ xin, float* __restrict__ xout,
                              int* __restrict__ newid, int npg, int k) {
    const int j = blockIdx.x * 8 + (threadIdx.x >> 5);
    if (j >= BGR_ * k) return;
    const int g = j / k, jj = j - g * k;
    const int srcpos = g * npg + jj;
    const int orig = sidx[srcpos];
    const float val = scores[orig];
    const int lane = threadIdx.x & 31;
    float4 v = *(const float4*)(xin + (size_t)orig * CC_ + lane * 4);
    v.x *= val; v.y *= val; v.z *= val; v.w *= val;
    *(float4*)(xout + (size_t)j * CC_ + lane * 4) = v;
    if (lane == 0) newid[orig] = j;
}

// ---------------- edge remap after pooling ----------------
__global__ void remap_kernel(const int* __restrict__ src, const int* __restrict__ dst,
                             const int* __restrict__ newid,
                             int* __restrict__ src2, int* __restrict__ dst2,
                             unsigned char* __restrict__ mask2) {
    const int e = blockIdx.x * blockDim.x + threadIdx.x;
    if (e >= EDG_) return;
    const int s = newid[src[e]];
    const int d = newid[dst[e]];
    const bool ok = (s >= 0) && (d >= 0);
    src2[e] = s; dst2[e] = d; mask2[e] = ok ? 1 : 0;
}

// ---------------- per-graph mean pooling: parallel partial sums ----------
// grid = (BGR_ * blocksPerGraph), 128 threads (one per column).
#define MEAN_BPG 16
__global__ void mean_part_kernel(const float* __restrict__ x, float* __restrict__ out, int k) {
    const int b = blockIdx.x / MEAN_BPG;
    const int chunk = blockIdx.x % MEAN_BPG;
    const int rows = (k + MEAN_BPG - 1) / MEAN_BPG;
    const int r0 = chunk * rows;
    const int r1 = (r0 + rows < k) ? (r0 + rows) : k;
    const int col = threadIdx.x;  // 0..127
    float s = 0.f;
    for (int r = r0; r < r1; ++r)
        s += x[((size_t)b * k + r) * CC_ + col];
    atomicAdd(&out[b * CC_ + col], s);
}

// ---------------- final MLP head (single block) ----------------
// out1/out2 hold SUMS; divide by k here (mean feeds only the head).
__global__ void head_kernel(const float* __restrict__ out1, const float* __restrict__ out2,
                            const float* __restrict__ Wg, const float* __restrict__ bg,
                            const float* __restrict__ Wr1, const float* __restrict__ br1,
                            const float* __restrict__ gg1, const float* __restrict__ be1,
                            const float* __restrict__ Wr2, const float* __restrict__ br2,
                            const float* __restrict__ gg2, const float* __restrict__ be2,
                            const float* __restrict__ Wout, float* __restrict__ out) {
    __shared__ float cat[8][256];
    __shared__ float gmat[8][128];
    __shared__ float r1[8][64];
    __shared__ float r2[8][32];
    const int tid = threadIdx.x;  // 256 threads
    for (int i = tid; i < 8 * 128; i += 256) {
        const int b = i >> 7, c = i & 127;
        cat[b][c]       = out1[i] / (float)KK1_;
        cat[b][c + 128] = out2[i] / (float)KK2_;
    }
    __syncthreads();
    const float inv = 1.0f / sqrtf(1.0f + 1e-5f);
    if (tid < 128) {
        for (int b = 0; b < 8; b++) {
            float s = 0.f;
            for (int k = 0; k < 256; k++) s = fmaf(cat[b][k], Wg[k * 128 + tid], s);
            gmat[b][tid] = s + bg[tid];
        }
    }
    __syncthreads();
    if (tid < 64) {
        for (int b = 0; b < 8; b++) {
            float s = 0.f;
            for (int k = 0; k < 128; k++) s = fmaf(gmat[b][k], Wr1[k * 64 + tid], s);
            s = (s + br1[tid]) * inv * gg1[tid] + be1[tid];
            r1[b][tid] = fmaxf(s, 0.f);
        }
    }
    __syncthreads();
    if (tid < 32) {
        for (int b = 0; b < 8; b++) {
            float s = 0.f;
            for (int k = 0; k < 64; k++) s = fmaf(r1[b][k], Wr2[k * 32 + tid], s);
            s = (s + br2[tid]) * inv * gg2[tid] + be2[tid];
            r2[b][tid] = fmaxf(s, 0.f);
        }
    }
    __syncthreads();
    if (tid < 32) {
        const int b = tid >> 2, j = tid & 3;
        float s = 0.f;
        for (int k = 0; k < 32; k++) s = fmaf(r2[b][k], Wout[k * 4 + j], s);
        out[b * 4 + j] = s;
    }
}

// ---------------- host orchestration ----------------
extern "C" void kernel_launch(void* const* d_in, const int* in_sizes, int n_in,
                              void* d_out, int out_size) {
    const float* x    = (const float*)d_in[0];
    const int*   ei   = (const int*)d_in[1];
    const int*   src  = ei;
    const int*   dst  = ei + EDG_;
    const float* W0   = (const float*)d_in[3];
    const float* b0   = (const float*)d_in[4];
    const float* W1a  = (const float*)d_in[5];
    const float* b1a  = (const float*)d_in[6];
    const float* W1b  = (const float*)d_in[7];
    const float* b1b  = (const float*)d_in[8];
    const float* Wrel1  = (const float*)d_in[9];
    const float* brel1  = (const float*)d_in[10];
    const float* Wroot1 = (const float*)d_in[11];
    const float* W2a  = (const float*)d_in[12];
    const float* b2a  = (const float*)d_in[13];
    const float* W2b  = (const float*)d_in[14];
    const float* b2b  = (const float*)d_in[15];
    const float* Wrel2  = (const float*)d_in[16];
    const float* brel2  = (const float*)d_in[17];
    const float* Wroot2 = (const float*)d_in[18];
    const float* Wg   = (const float*)d_in[19];
    const float* bg   = (const float*)d_in[20];
    const float* Wr1  = (const float*)d_in[21];
    const float* br1  = (const float*)d_in[22];
    const float* gg1  = (const float*)d_in[23];
    const float* be1  = (const float*)d_in[24];
    const float* Wr2  = (const float*)d_in[25];
    const float* br2  = (const float*)d_in[26];
    const float* gg2  = (const float*)d_in[27];
    const float* be2  = (const float*)d_in[28];
    const float* Wout = (const float*)d_in[29];

    float *bufA, *bufB, *bufC, *scores, *srel, *sroot, *ssum, *o1, *o2;
    unsigned long long *key64, *key64B;
    int *iota, *sidx, *newid, *src2, *dst2;
    unsigned char *mask2, *cubtmp;
    cudaGetSymbolAddress((void**)&bufA, g_bufA);
    cudaGetSymbolAddress((void**)&bufB, g_bufB);
    cudaGetSymbolAddress((void**)&bufC, g_bufC);
    cudaGetSymbolAddress((void**)&scores, g_scores);
    cudaGetSymbolAddress((void**)&srel, g_srel);
    cudaGetSymbolAddress((void**)&sroot, g_sroot);
    cudaGetSymbolAddress((void**)&ssum, g_ssum);
    cudaGetSymbolAddress((void**)&key64, g_key64);
    cudaGetSymbolAddress((void**)&key64B, g_key64B);
    cudaGetSymbolAddress((void**)&iota, g_iota);
    cudaGetSymbolAddress((void**)&sidx, g_sidx);
    cudaGetSymbolAddress((void**)&newid, g_newid);
    cudaGetSymbolAddress((void**)&src2, g_src2);
    cudaGetSymbolAddress((void**)&dst2, g_dst2);
    cudaGetSymbolAddress((void**)&mask2, g_mask2);
    cudaGetSymbolAddress((void**)&o1, g_out1);
    cudaGetSymbolAddress((void**)&o2, g_out2);
    cudaGetSymbolAddress((void**)&cubtmp, g_cubtmp);

    const int n4_full = NB_ * CC_ / 4;
    const int n4_l2   = NB1_ * CC_ / 4;

    // ---- stage 0: h0 = relu(x @ W0 + b0) -> bufA
    gemm_kernel<FF_, true><<<NB_ / 64, 256>>>(x, W0, b0, bufA);

    // ---- GIN layer 1
    copy4_kernel<<<4096, 256>>>((const float4*)bufA, (float4*)bufB, n4_full);
    scatter_kernel<<<EDG_ / 8, 256>>>(bufA, src, dst, nullptr, bufB, EDG_);
    gemm_kernel<CC_, true ><<<NB_ / 64, 256>>>(bufB, W1a, b1a, bufC);
    gemm_kernel<CC_, false><<<NB_ / 64, 256>>>(bufC, W1b, b1b, bufB);  // h1 = bufB

    // ---- SAGPool 1
    score_pre_kernel<<<(NB_ + 255) / 256, 256>>>(bufB, Wrel1, Wroot1, srel, sroot, NB_);
    zerof_kernel<<<(NB_ + 255) / 256, 256>>>(ssum, NB_);
    scatter_scalar_kernel<<<(EDG_ + 255) / 256, 256>>>(srel, src, dst, nullptr, ssum, EDG_);
    score_fin_kernel<<<(NB_ + 255) / 256, 256>>>(ssum, sroot, brel1, scores, key64, iota, NPG_, NB_);
    {
        size_t tmp = 0;
        cub::DeviceRadixSort::SortPairs(nullptr, tmp, key64, key64B, iota, sidx, NB_, 0, 35);
        if (tmp > sizeof(g_cubtmp)) tmp = sizeof(g_cubtmp);
        cub::DeviceRadixSort::SortPairs((void*)cubtmp, tmp, key64, key64B, iota, sidx, NB_, 0, 35);
    }
    filln1_kernel<<<(NB_ + 255) / 256, 256>>>(newid, NB_);
    select_kernel<<<NB1_ / 8, 256>>>(scores, sidx, bufB, bufC, newid, NPG_, KK1_);  // h2 = bufC
    zerof_kernel<<<4, 256>>>(o1, BGR_ * CC_);
    mean_part_kernel<<<BGR_ * MEAN_BPG, 128>>>(bufC, o1, KK1_);
    remap_kernel<<<EDG_ / 256, 256>>>(src, dst, newid, src2, dst2, mask2);

    // ---- GIN layer 2
    copy4_kernel<<<4096, 256>>>((const float4*)bufC, (float4*)bufA, n4_l2);
    scatter_kernel<<<EDG_ / 8, 256>>>(bufC, src2, dst2, mask2, bufA, EDG_);
    gemm_kernel<CC_, true ><<<NB1_ / 64, 256>>>(bufA, W2a, b2a, bufB);
    gemm_kernel<CC_, false><<<NB1_ / 64, 256>>>(bufB, W2b, b2b, bufC);  // h3 = bufC

    // ---- SAGPool 2
    score_pre_kernel<<<(NB1_ + 255) / 256, 256>>>(bufC, Wrel2, Wroot2, srel, sroot, NB1_);
    zerof_kernel<<<(NB1_ + 255) / 256, 256>>>(ssum, NB1_);
    scatter_scalar_kernel<<<(EDG_ + 255) / 256, 256>>>(srel, src2, dst2, mask2, ssum, EDG_);
    score_fin_kernel<<<(NB1_ + 255) / 256, 256>>>(ssum, sroot, brel2, scores, key64, iota, KK1_, NB1_);
    {
        size_t tmp = 0;
        cub::DeviceRadixSort::SortPairs(nullptr, tmp, key64, key64B, iota, sidx, NB1_, 0, 35);
        if (tmp > sizeof(g_cubtmp)) tmp = sizeof(g_cubtmp);
        cub::DeviceRadixSort::SortPairs((void*)cubtmp, tmp, key64, key64B, iota, sidx, NB1_, 0, 35);
    }
    select_kernel<<<NB2_ / 8, 256>>>(scores, sidx, bufC, bufB, newid, KK1_, KK2_);  // h4 = bufB
    zerof_kernel<<<4, 256>>>(o2, BGR_ * CC_);
    mean_part_kernel<<<BGR_ * MEAN_BPG, 128>>>(bufB, o2, KK2_);

    // ---- head
    head_kernel<<<1, 256>>>(o1, o2, Wg, bg, Wr1, br1, gg1, be1,
                            Wr2, br2, gg2, be2, Wout, (float*)d_out);
}

// round 9
// speedup vs baseline: 1.3675x; 1.0055x over previous
#include <cuda_runtime.h>
#include <cub/cub.cuh>

// Problem constants
#define NB_   80000      // B*N nodes layer 0/1
#define BGR_  8          // graphs
#define NPG_  10000      // nodes per graph (layer 1)
#define EDG_  640000     // edges
#define CC_   128        // channels
#define FF_   64         // input features
#define KK1_  6000       // kept after pool1 (per graph)
#define NB1_  48000      // B*KK1
#define KK2_  3600       // kept after pool2 (per graph)
#define NB2_  28800      // B*KK2

// ---------------- static device scratch (no allocs allowed) ----------------
__device__ float g_bufA[NB_ * CC_];
__device__ float g_bufB[NB_ * CC_];
__device__ float g_bufC[NB_ * CC_];
__device__ float g_scores[NB_];
__device__ float g_srel[NB_];
__device__ float g_sroot[NB_];
__device__ float g_ssum[NB_];
__device__ unsigned long long g_key64[NB_];
__device__ unsigned long long g_key64B[NB_];
__device__ int   g_iota[NB_];
__device__ int   g_sidx[NB_];
__device__ int   g_newid[NB_];
__device__ int   g_src2[EDG_];
__device__ int   g_dst2[EDG_];
__device__ unsigned char g_mask2[EDG_];
__device__ float g_out1[BGR_ * CC_];
__device__ float g_out2[BGR_ * CC_];
__device__ unsigned char g_cubtmp[1u << 24];  // 16 MB cub temp

// ---------------- XLA-GPU (MLIR math polynomial approximation) tanh -------
__device__ __forceinline__ float xla_tanh(float ax) {
    const float plus_clamp  = 7.99881172180175781f;
    const float minus_clamp = -7.99881172180175781f;
    const float tiny = 0.0004f;
    const float alpha_1  = 4.89352455891786e-03f;
    const float alpha_3  = 6.37261928875436e-04f;
    const float alpha_5  = 1.48572235717979e-05f;
    const float alpha_7  = 5.12229709037114e-08f;
    const float alpha_9  = -8.60467152213735e-11f;
    const float alpha_11 = 2.00018790482477e-13f;
    const float alpha_13 = -2.76076847742355e-16f;
    const float beta_0 = 4.89352518554385e-03f;
    const float beta_2 = 2.26843463243900e-03f;
    const float beta_4 = 1.18534705686654e-04f;
    const float beta_6 = 1.19825839466702e-06f;

    float x = fminf(fmaxf(ax, minus_clamp), plus_clamp);
    float x2 = x * x;
    float p = fmaf(x2, alpha_13, alpha_11);
    p = fmaf(x2, p, alpha_9);
    p = fmaf(x2, p, alpha_7);
    p = fmaf(x2, p, alpha_5);
    p = fmaf(x2, p, alpha_3);
    p = fmaf(x2, p, alpha_1);
    p = x * p;
    float q = fmaf(x2, beta_6, beta_4);
    q = fmaf(x2, q, beta_2);
    q = fmaf(x2, q, beta_0);
    float r = p / q;
    return (fabsf(ax) < tiny) ? ax : r;
}

// ---------------- GEMM: [M x K] @ [K x 128] + bias (+relu), opt dual store
template <int K, bool RELU, bool DUAL>
__global__ void __launch_bounds__(256) gemm_kernel(const float* __restrict__ A,
                                                   const float* __restrict__ W,
                                                   const float* __restrict__ bias,
                                                   float* __restrict__ out,
                                                   float* __restrict__ out2) {
    __shared__ float As[64][36];
    __shared__ float Bs[32][128];

    const int tid  = threadIdx.x;
    const int row0 = blockIdx.x * 64;
    const int warp = tid >> 5, lane = tid & 31;
    const int r0 = warp * 8;
    const int c0 = lane * 4;

    float acc[8][4];
#pragma unroll
    for (int i = 0; i < 8; i++)
#pragma unroll
        for (int j = 0; j < 4; j++) acc[i][j] = 0.f;

    for (int k0 = 0; k0 < K; k0 += 32) {
        {
            const int r  = tid >> 3;
            const int k4 = (tid & 7) * 4;
            float4 v0 = *(const float4*)(A + (size_t)(row0 + r) * K + k0 + k4);
            float4 v1 = *(const float4*)(A + (size_t)(row0 + r + 32) * K + k0 + k4);
            *(float4*)&As[r][k4]      = v0;
            *(float4*)&As[r + 32][k4] = v1;
        }
#pragma unroll
        for (int it = 0; it < 4; ++it) {
            const int f  = tid + it * 256;
            const int k  = f >> 5;
            const int c4 = (f & 31) * 4;
            *(float4*)&Bs[k][c4] = *(const float4*)(W + (size_t)(k0 + k) * 128 + c4);
        }
        __syncthreads();
#pragma unroll
        for (int kk = 0; kk < 32; ++kk) {
            const float4 b = *(const float4*)&Bs[kk][c0];
#pragma unroll
            for (int i = 0; i < 8; i++) {
                const float a = As[r0 + i][kk];
                acc[i][0] = fmaf(a, b.x, acc[i][0]);
                acc[i][1] = fmaf(a, b.y, acc[i][1]);
                acc[i][2] = fmaf(a, b.z, acc[i][2]);
                acc[i][3] = fmaf(a, b.w, acc[i][3]);
            }
        }
        __syncthreads();
    }

    const float4 bv = *(const float4*)(bias + c0);
#pragma unroll
    for (int i = 0; i < 8; i++) {
        float4 o;
        o.x = acc[i][0] + bv.x;
        o.y = acc[i][1] + bv.y;
        o.z = acc[i][2] + bv.z;
        o.w = acc[i][3] + bv.w;
        if (RELU) {
            o.x = fmaxf(o.x, 0.f); o.y = fmaxf(o.y, 0.f);
            o.z = fmaxf(o.z, 0.f); o.w = fmaxf(o.w, 0.f);
        }
        const size_t off = (size_t)(row0 + r0 + i) * 128 + c0;
        *(float4*)(out + off) = o;
        if (DUAL) *(float4*)(out2 + off) = o;
    }
}

// ---------------- edge vector scatter-add (1 warp / edge) -----------------
__global__ void scatter_kernel(const float* __restrict__ x, const int* __restrict__ src,
                               const int* __restrict__ dst,
                               const unsigned char* __restrict__ mask,
                               float* __restrict__ agg, int nE) {
    const int e = blockIdx.x * 8 + (threadIdx.x >> 5);
    if (e >= nE) return;
    if (mask && !mask[e]) return;
    const int lane = threadIdx.x & 31;
    const int s = src[e], d = dst[e];
    float4 v = *(const float4*)(x + (size_t)s * CC_ + lane * 4);
    atomicAdd((float4*)(agg + (size_t)d * CC_ + lane * 4), v);  // sm_90+ vector RED
}

// ---------------- scalar edge scatter-add for scores ----------------------
__global__ void scatter_scalar_kernel(const float* __restrict__ srel,
                                      const int* __restrict__ src,
                                      const int* __restrict__ dst,
                                      const unsigned char* __restrict__ mask,
                                      float* __restrict__ ssum, int nE) {
    const int e = blockIdx.x * blockDim.x + threadIdx.x;
    if (e >= nE) return;
    if (mask && !mask[e]) return;
    atomicAdd(&ssum[dst[e]], srel[src[e]]);
}

// ---------------- score pre-pass: srel/sroot dots, zero ssum --------------
__global__ void score_pre_kernel(const float* __restrict__ x,
                                 const float* __restrict__ Wrel,
                                 const float* __restrict__ Wroot,
                                 float* __restrict__ srel, float* __restrict__ sroot,
                                 float* __restrict__ ssum, int n) {
    const int node = blockIdx.x * blockDim.x + threadIdx.x;
    if (node >= n) return;
    const float* xx = x + (size_t)node * CC_;
    float t1 = 0.f, t2 = 0.f;
#pragma unroll 16
    for (int c = 0; c < CC_; ++c) t1 = fmaf(xx[c], Wrel[c], t1);
#pragma unroll 16
    for (int c = 0; c < CC_; ++c) t2 = fmaf(xx[c], Wroot[c], t2);
    srel[node] = t1;
    sroot[node] = t2;
    ssum[node] = 0.f;
}

// ---------------- score finalize + composite sort key + inits -------------
// key64 = (graph_id << 32) | desc_encode(score): stable ascending radix sort
// == per-graph descending-score order with ascending-index tie-break.
// Also: optional newid=-1 init, and zeroing of a 1024-float output buffer.
__global__ void score_fin_kernel(const float* __restrict__ ssum,
                                 const float* __restrict__ sroot,
                                 const float* __restrict__ brel,
                                 float* __restrict__ scores,
                                 unsigned long long* __restrict__ key64,
                                 int* __restrict__ iota,
                                 int* __restrict__ newid_init,
                                 float* __restrict__ ozero,
                                 int npg, int n) {
    const int node = blockIdx.x * blockDim.x + threadIdx.x;
    if (node >= n) return;
    const float sc = xla_tanh((ssum[node] + brel[0]) + sroot[node]);
    scores[node] = sc;
    unsigned int u = __float_as_uint(sc);
    unsigned int e = (u & 0x80000000u) ? ~u : (u | 0x80000000u); // ascending encode
    unsigned int kd = ~e;                                         // descending
    const unsigned int g = (unsigned int)(node / npg);
    key64[node] = ((unsigned long long)g << 32) | (unsigned long long)kd;
    iota[node] = node;
    if (newid_init) newid_init[node] = -1;
    if (ozero && node < BGR_ * CC_) ozero[node] = 0.f;
}

// ---------------- selection/gather after sort (1 warp / kept node) -------
// Optional dual store (xout2 = base buffer for the next layer's scatter).
__global__ void select_kernel(const float* __restrict__ scores, const int* __restrict__ sidx,
                              const float* __restrict__ xin, float* __restrict__ xout,
                              float* __restrict__ xout2,
                              int* __restrict__ newid, int npg, int k) {
    const int j = blockIdx.x * 8 + (threadIdx.x >> 5);
    if (j >= BGR_ * k) return;
    const int g = j / k, jj = j - g * k;
    const int srcpos = g * npg + jj;
    const int orig = sidx[srcpos];
    const float val = scores[orig];
    const int lane = threadIdx.x & 31;
    float4 v = *(const float4*)(xin + (size_t)orig * CC_ + lane * 4);
    v.x *= val; v.y *= val; v.z *= val; v.w *= val;
    const size_t off = (size_t)j * CC_ + lane * 4;
    *(float4*)(xout + off) = v;
    if (xout2) *(float4*)(xout2 + off) = v;
    if (lane == 0) newid[orig] = j;
}

// ---------------- edge remap after pooling ----------------
__global__ void remap_kernel(const int* __restrict__ src, const int* __restrict__ dst,
                             const int* __restrict__ newid,
                             int* __restrict__ src2, int* __restrict__ dst2,
                             unsigned char* __restrict__ mask2) {
    const int e = blockIdx.x * blockDim.x + threadIdx.x;
    if (e >= EDG_) return;
    const int s = newid[src[e]];
    const int d = newid[dst[e]];
    const bool ok = (s >= 0) && (d >= 0);
    src2[e] = s; dst2[e] = d; mask2[e] = ok ? 1 : 0;
}

// ---------------- per-graph mean pooling: parallel partial sums ----------
#define MEAN_BPG 16
__global__ void mean_part_kernel(const float* __restrict__ x, float* __restrict__ out, int k) {
    const int b = blockIdx.x / MEAN_BPG;
    const int chunk = blockIdx.x % MEAN_BPG;
    const int rows = (k + MEAN_BPG - 1) / MEAN_BPG;
    const int r0 = chunk * rows;
    const int r1 = (r0 + rows < k) ? (r0 + rows) : k;
    const int col = threadIdx.x;  // 0..127
    float s = 0.f;
    for (int r = r0; r < r1; ++r)
        s += x[((size_t)b * k + r) * CC_ + col];
    atomicAdd(&out[b * CC_ + col], s);
}

// ---------------- final MLP head (single block) ----------------
__global__ void head_kernel(const float* __restrict__ out1, const float* __restrict__ out2,
                            const float* __restrict__ Wg, const float* __restrict__ bg,
                            const float* __restrict__ Wr1, const float* __restrict__ br1,
                            const float* __restrict__ gg1, const float* __restrict__ be1,
                            const float* __restrict__ Wr2, const float* __restrict__ br2,
                            const float* __restrict__ gg2, const float* __restrict__ be2,
                            const float* __restrict__ Wout, float* __restrict__ out) {
    __shared__ float cat[8][256];
    __shared__ float gmat[8][128];
    __shared__ float r1[8][64];
    __shared__ float r2[8][32];
    const int tid = threadIdx.x;  // 256 threads
    for (int i = tid; i < 8 * 128; i += 256) {
        const int b = i >> 7, c = i & 127;
        cat[b][c]       = out1[i] / (float)KK1_;
        cat[b][c + 128] = out2[i] / (float)KK2_;
    }
    __syncthreads();
    const float inv = 1.0f / sqrtf(1.0f + 1e-5f);
    if (tid < 128) {
        for (int b = 0; b < 8; b++) {
            float s = 0.f;
            for (int k = 0; k < 256; k++) s = fmaf(cat[b][k], Wg[k * 128 + tid], s);
            gmat[b][tid] = s + bg[tid];
        }
    }
    __syncthreads();
    if (tid < 64) {
        for (int b = 0; b < 8; b++) {
            float s = 0.f;
            for (int k = 0; k < 128; k++) s = fmaf(gmat[b][k], Wr1[k * 64 + tid], s);
            s = (s + br1[tid]) * inv * gg1[tid] + be1[tid];
            r1[b][tid] = fmaxf(s, 0.f);
        }
    }
    __syncthreads();
    if (tid < 32) {
        for (int b = 0; b < 8; b++) {
            float s = 0.f;
            for (int k = 0; k < 64; k++) s = fmaf(r1[b][k], Wr2[k * 32 + tid], s);
            s = (s + br2[tid]) * inv * gg2[tid] + be2[tid];
            r2[b][tid] = fmaxf(s, 0.f);
        }
    }
    __syncthreads();
    if (tid < 32) {
        const int b = tid >> 2, j = tid & 3;
        float s = 0.f;
        for (int k = 0; k < 32; k++) s = fmaf(r2[b][k], Wout[k * 4 + j], s);
        out[b * 4 + j] = s;
    }
}

// ---------------- host orchestration ----------------
extern "C" void kernel_launch(void* const* d_in, const int* in_sizes, int n_in,
                              void* d_out, int out_size) {
    const float* x    = (const float*)d_in[0];
    const int*   ei   = (const int*)d_in[1];
    const int*   src  = ei;
    const int*   dst  = ei + EDG_;
    const float* W0   = (const float*)d_in[3];
    const float* b0   = (const float*)d_in[4];
    const float* W1a  = (const float*)d_in[5];
    const float* b1a  = (const float*)d_in[6];
    const float* W1b  = (const float*)d_in[7];
    const float* b1b  = (const float*)d_in[8];
    const float* Wrel1  = (const float*)d_in[9];
    const float* brel1  = (const float*)d_in[10];
    const float* Wroot1 = (const float*)d_in[11];
    const float* W2a  = (const float*)d_in[12];
    const float* b2a  = (const float*)d_in[13];
    const float* W2b  = (const float*)d_in[14];
    const float* b2b  = (const float*)d_in[15];
    const float* Wrel2  = (const float*)d_in[16];
    const float* brel2  = (const float*)d_in[17];
    const float* Wroot2 = (const float*)d_in[18];
    const float* Wg   = (const float*)d_in[19];
    const float* bg   = (const float*)d_in[20];
    const float* Wr1  = (const float*)d_in[21];
    const float* br1  = (const float*)d_in[22];
    const float* gg1  = (const float*)d_in[23];
    const float* be1  = (const float*)d_in[24];
    const float* Wr2  = (const float*)d_in[25];
    const float* br2  = (const float*)d_in[26];
    const float* gg2  = (const float*)d_in[27];
    const float* be2  = (const float*)d_in[28];
    const float* Wout = (const float*)d_in[29];

    float *bufA, *bufB, *bufC, *scores, *srel, *sroot, *ssum, *o1, *o2;
    unsigned long long *key64, *key64B;
    int *iota, *sidx, *newid, *src2, *dst2;
    unsigned char *mask2, *cubtmp;
    cudaGetSymbolAddress((void**)&bufA, g_bufA);
    cudaGetSymbolAddress((void**)&bufB, g_bufB);
    cudaGetSymbolAddress((void**)&bufC, g_bufC);
    cudaGetSymbolAddress((void**)&scores, g_scores);
    cudaGetSymbolAddress((void**)&srel, g_srel);
    cudaGetSymbolAddress((void**)&sroot, g_sroot);
    cudaGetSymbolAddress((void**)&ssum, g_ssum);
    cudaGetSymbolAddress((void**)&key64, g_key64);
    cudaGetSymbolAddress((void**)&key64B, g_key64B);
    cudaGetSymbolAddress((void**)&iota, g_iota);
    cudaGetSymbolAddress((void**)&sidx, g_sidx);
    cudaGetSymbolAddress((void**)&newid, g_newid);
    cudaGetSymbolAddress((void**)&src2, g_src2);
    cudaGetSymbolAddress((void**)&dst2, g_dst2);
    cudaGetSymbolAddress((void**)&mask2, g_mask2);
    cudaGetSymbolAddress((void**)&o1, g_out1);
    cudaGetSymbolAddress((void**)&o2, g_out2);
    cudaGetSymbolAddress((void**)&cubtmp, g_cubtmp);

    // ---- stage 0: h0 = relu(x @ W0 + b0) -> bufA AND bufB (scatter base)
    gemm_kernel<FF_, true, true><<<NB_ / 64, 256>>>(x, W0, b0, bufA, bufB);

    // ---- GIN layer 1: bufB += segsum(h0) ; h1 = nn(bufB)
    scatter_kernel<<<EDG_ / 8, 256>>>(bufA, src, dst, nullptr, bufB, EDG_);
    gemm_kernel<CC_, true , false><<<NB_ / 64, 256>>>(bufB, W1a, b1a, bufC, nullptr);
    gemm_kernel<CC_, false, false><<<NB_ / 64, 256>>>(bufC, W1b, b1b, bufB, nullptr);  // h1 = bufB

    // ---- SAGPool 1
    score_pre_kernel<<<(NB_ + 255) / 256, 256>>>(bufB, Wrel1, Wroot1, srel, sroot, ssum, NB_);
    scatter_scalar_kernel<<<(EDG_ + 255) / 256, 256>>>(srel, src, dst, nullptr, ssum, EDG_);
    score_fin_kernel<<<(NB_ + 255) / 256, 256>>>(ssum, sroot, brel1, scores, key64, iota,
                                                 newid, o1, NPG_, NB_);
    {
        size_t tmp = 0;
        cub::DeviceRadixSort::SortPairs(nullptr, tmp, key64, key64B, iota, sidx, NB_, 0, 35);
        if (tmp > sizeof(g_cubtmp)) tmp = sizeof(g_cubtmp);
        cub::DeviceRadixSort::SortPairs((void*)cubtmp, tmp, key64, key64B, iota, sidx, NB_, 0, 35);
    }
    // h2 -> bufC AND bufA (layer-2 scatter base)
    select_kernel<<<NB1_ / 8, 256>>>(scores, sidx, bufB, bufC, bufA, newid, NPG_, KK1_);
    mean_part_kernel<<<BGR_ * MEAN_BPG, 128>>>(bufC, o1, KK1_);
    remap_kernel<<<EDG_ / 256, 256>>>(src, dst, newid, src2, dst2, mask2);

    // ---- GIN layer 2: bufA += segsum(h2) ; h3 = nn(bufA)
    scatter_kernel<<<EDG_ / 8, 256>>>(bufC, src2, dst2, mask2, bufA, EDG_);
    gemm_kernel<CC_, true , false><<<NB1_ / 64, 256>>>(bufA, W2a, b2a, bufB, nullptr);
    gemm_kernel<CC_, false, false><<<NB1_ / 64, 256>>>(bufB, W2b, b2b, bufC, nullptr);  // h3 = bufC

    // ---- SAGPool 2
    score_pre_kernel<<<(NB1_ + 255) / 256, 256>>>(bufC, Wrel2, Wroot2, srel, sroot, ssum, NB1_);
    scatter_scalar_kernel<<<(EDG_ + 255) / 256, 256>>>(srel, src2, dst2, mask2, ssum, EDG_);
    score_fin_kernel<<<(NB1_ + 255) / 256, 256>>>(ssum, sroot, brel2, scores, key64, iota,
                                                  nullptr, o2, KK1_, NB1_);
    {
        size_t tmp = 0;
        cub::DeviceRadixSort::SortPairs(nullptr, tmp, key64, key64B, iota, sidx, NB1_, 0, 35);
        if (tmp > sizeof(g_cubtmp)) tmp = sizeof(g_cubtmp);
        cub::DeviceRadixSort::SortPairs((void*)cubtmp, tmp, key64, key64B, iota, sidx, NB1_, 0, 35);
    }
    select_kernel<<<NB2_ / 8, 256>>>(scores, sidx, bufC, bufB, nullptr, newid, KK1_, KK2_);
    mean_part_kernel<<<BGR_ * MEAN_BPG, 128>>>(bufB, o2, KK2_);

    // ---- head
    head_kernel<<<1, 256>>>(o1, o2, Wg, bg, Wr1, br1, gg1, be1,
                            Wr2, br2, gg2, be2, Wout, (float*)d_out);
}

// round 10
// speedup vs baseline: 1.4787x; 1.0813x over previous
#include <cuda_runtime.h>
#include <cub/cub.cuh>

// Problem constants
#define NB_   80000      // B*N nodes layer 0/1
#define BGR_  8          // graphs
#define NPG_  10000      // nodes per graph (layer 1)
#define EDG_  640000     // edges
#define CC_   128        // channels
#define FF_   64         // input features
#define KK1_  6000       // kept after pool1 (per graph)
#define NB1_  48000      // B*KK1
#define KK2_  3600       // kept after pool2 (per graph)
#define NB2_  28800      // B*KK2

// ---------------- static device scratch (no allocs allowed) ----------------
__device__ float g_bufA[NB_ * CC_];
__device__ float g_bufB[NB_ * CC_];
__device__ float g_bufC[NB_ * CC_];
__device__ float g_scores[NB_];
__device__ float g_srel[NB_];
__device__ float g_sroot[NB_];
__device__ float g_ssum[NB_];
__device__ unsigned long long g_key64[NB_];
__device__ unsigned long long g_key64B[NB_];
__device__ int   g_iota[NB_];
__device__ int   g_sidx[NB_];
__device__ int   g_newid[NB_];
__device__ int   g_src2[EDG_];
__device__ int   g_dst2[EDG_];
__device__ unsigned char g_mask2[EDG_];
__device__ float g_out1[BGR_ * CC_];
__device__ float g_out2[BGR_ * CC_];
__device__ unsigned char g_cubtmp[1u << 24];  // 16 MB cub temp

// ---------------- XLA-GPU (MLIR math polynomial approximation) tanh -------
__device__ __forceinline__ float xla_tanh(float ax) {
    const float plus_clamp  = 7.99881172180175781f;
    const float minus_clamp = -7.99881172180175781f;
    const float tiny = 0.0004f;
    const float alpha_1  = 4.89352455891786e-03f;
    const float alpha_3  = 6.37261928875436e-04f;
    const float alpha_5  = 1.48572235717979e-05f;
    const float alpha_7  = 5.12229709037114e-08f;
    const float alpha_9  = -8.60467152213735e-11f;
    const float alpha_11 = 2.00018790482477e-13f;
    const float alpha_13 = -2.76076847742355e-16f;
    const float beta_0 = 4.89352518554385e-03f;
    const float beta_2 = 2.26843463243900e-03f;
    const float beta_4 = 1.18534705686654e-04f;
    const float beta_6 = 1.19825839466702e-06f;

    float x = fminf(fmaxf(ax, minus_clamp), plus_clamp);
    float x2 = x * x;
    float p = fmaf(x2, alpha_13, alpha_11);
    p = fmaf(x2, p, alpha_9);
    p = fmaf(x2, p, alpha_7);
    p = fmaf(x2, p, alpha_5);
    p = fmaf(x2, p, alpha_3);
    p = fmaf(x2, p, alpha_1);
    p = x * p;
    float q = fmaf(x2, beta_6, beta_4);
    q = fmaf(x2, q, beta_2);
    q = fmaf(x2, q, beta_0);
    float r = p / q;
    return (fabsf(ax) < tiny) ? ax : r;
}

// ---------------- GEMM (stage 0): [M x K] @ [K x 128] + bias + relu -------
template <int K, bool RELU, bool DUAL>
__global__ void __launch_bounds__(256) gemm_kernel(const float* __restrict__ A,
                                                   const float* __restrict__ W,
                                                   const float* __restrict__ bias,
                                                   float* __restrict__ out,
                                                   float* __restrict__ out2) {
    __shared__ float As[64][36];
    __shared__ float Bs[32][128];

    const int tid  = threadIdx.x;
    const int row0 = blockIdx.x * 64;
    const int warp = tid >> 5, lane = tid & 31;
    const int r0 = warp * 8;
    const int c0 = lane * 4;

    float acc[8][4];
#pragma unroll
    for (int i = 0; i < 8; i++)
#pragma unroll
        for (int j = 0; j < 4; j++) acc[i][j] = 0.f;

    for (int k0 = 0; k0 < K; k0 += 32) {
        {
            const int r  = tid >> 3;
            const int k4 = (tid & 7) * 4;
            float4 v0 = *(const float4*)(A + (size_t)(row0 + r) * K + k0 + k4);
            float4 v1 = *(const float4*)(A + (size_t)(row0 + r + 32) * K + k0 + k4);
            *(float4*)&As[r][k4]      = v0;
            *(float4*)&As[r + 32][k4] = v1;
        }
#pragma unroll
        for (int it = 0; it < 4; ++it) {
            const int f  = tid + it * 256;
            const int k  = f >> 5;
            const int c4 = (f & 31) * 4;
            *(float4*)&Bs[k][c4] = *(const float4*)(W + (size_t)(k0 + k) * 128 + c4);
        }
        __syncthreads();
#pragma unroll
        for (int kk = 0; kk < 32; ++kk) {
            const float4 b = *(const float4*)&Bs[kk][c0];
#pragma unroll
            for (int i = 0; i < 8; i++) {
                const float a = As[r0 + i][kk];
                acc[i][0] = fmaf(a, b.x, acc[i][0]);
                acc[i][1] = fmaf(a, b.y, acc[i][1]);
                acc[i][2] = fmaf(a, b.z, acc[i][2]);
                acc[i][3] = fmaf(a, b.w, acc[i][3]);
            }
        }
        __syncthreads();
    }

    const float4 bv = *(const float4*)(bias + c0);
#pragma unroll
    for (int i = 0; i < 8; i++) {
        float4 o;
        o.x = acc[i][0] + bv.x;
        o.y = acc[i][1] + bv.y;
        o.z = acc[i][2] + bv.z;
        o.w = acc[i][3] + bv.w;
        if (RELU) {
            o.x = fmaxf(o.x, 0.f); o.y = fmaxf(o.y, 0.f);
            o.z = fmaxf(o.z, 0.f); o.w = fmaxf(o.w, 0.f);
        }
        const size_t off = (size_t)(row0 + r0 + i) * 128 + c0;
        *(float4*)(out + off) = o;
        if (DUAL) *(float4*)(out2 + off) = o;
    }
}

// ---------------- fused GIN nn: out = relu(A@Wa+ba) @ Wb + bb -------------
// 64-row tile, 256 threads, t1 kept in smem; per-element FMA chains are
// identical to the two separate GEMMs -> bit-identical output.
__global__ void __launch_bounds__(256) gin_kernel(const float* __restrict__ A,
                                                  const float* __restrict__ Wa,
                                                  const float* __restrict__ ba,
                                                  const float* __restrict__ Wb,
                                                  const float* __restrict__ bb,
                                                  float* __restrict__ out) {
    extern __shared__ char smem[];
    float (*As)[36]  = (float(*)[36])smem;                    //  9216 B
    float (*Bs)[128] = (float(*)[128])(smem + 9216);          // 16384 B
    float (*T1)[132] = (float(*)[132])(smem + 9216 + 16384);  // 33792 B

    const int tid  = threadIdx.x;
    const int row0 = blockIdx.x * 64;
    const int warp = tid >> 5, lane = tid & 31;
    const int r0 = warp * 8;
    const int c0 = lane * 4;

    float acc[8][4];
#pragma unroll
    for (int i = 0; i < 8; i++)
#pragma unroll
        for (int j = 0; j < 4; j++) acc[i][j] = 0.f;

    // ---- phase 1: t1 = relu(A@Wa + ba)
    for (int k0 = 0; k0 < CC_; k0 += 32) {
        {
            const int r  = tid >> 3;
            const int k4 = (tid & 7) * 4;
            float4 v0 = *(const float4*)(A + (size_t)(row0 + r) * CC_ + k0 + k4);
            float4 v1 = *(const float4*)(A + (size_t)(row0 + r + 32) * CC_ + k0 + k4);
            *(float4*)&As[r][k4]      = v0;
            *(float4*)&As[r + 32][k4] = v1;
        }
#pragma unroll
        for (int it = 0; it < 4; ++it) {
            const int f  = tid + it * 256;
            const int k  = f >> 5;
            const int c4 = (f & 31) * 4;
            *(float4*)&Bs[k][c4] = *(const float4*)(Wa + (size_t)(k0 + k) * 128 + c4);
        }
        __syncthreads();
#pragma unroll
        for (int kk = 0; kk < 32; ++kk) {
            const float4 b = *(const float4*)&Bs[kk][c0];
#pragma unroll
            for (int i = 0; i < 8; i++) {
                const float a = As[r0 + i][kk];
                acc[i][0] = fmaf(a, b.x, acc[i][0]);
                acc[i][1] = fmaf(a, b.y, acc[i][1]);
                acc[i][2] = fmaf(a, b.z, acc[i][2]);
                acc[i][3] = fmaf(a, b.w, acc[i][3]);
            }
        }
        __syncthreads();
    }
    {
        const float4 bv = *(const float4*)(ba + c0);
#pragma unroll
        for (int i = 0; i < 8; i++) {
            float4 o;
            o.x = fmaxf(acc[i][0] + bv.x, 0.f);
            o.y = fmaxf(acc[i][1] + bv.y, 0.f);
            o.z = fmaxf(acc[i][2] + bv.z, 0.f);
            o.w = fmaxf(acc[i][3] + bv.w, 0.f);
            *(float4*)&T1[r0 + i][c0] = o;
        }
    }

    // ---- phase 2: out = t1 @ Wb + bb
#pragma unroll
    for (int i = 0; i < 8; i++)
#pragma unroll
        for (int j = 0; j < 4; j++) acc[i][j] = 0.f;

    for (int k0 = 0; k0 < CC_; k0 += 32) {
#pragma unroll
        for (int it = 0; it < 4; ++it) {
            const int f  = tid + it * 256;
            const int k  = f >> 5;
            const int c4 = (f & 31) * 4;
            *(float4*)&Bs[k][c4] = *(const float4*)(Wb + (size_t)(k0 + k) * 128 + c4);
        }
        __syncthreads();   // also orders T1 writes before T1 reads (k0 == 0)
#pragma unroll
        for (int kk = 0; kk < 32; ++kk) {
            const float4 b = *(const float4*)&Bs[kk][c0];
#pragma unroll
            for (int i = 0; i < 8; i++) {
                const float a = T1[r0 + i][k0 + kk];
                acc[i][0] = fmaf(a, b.x, acc[i][0]);
                acc[i][1] = fmaf(a, b.y, acc[i][1]);
                acc[i][2] = fmaf(a, b.z, acc[i][2]);
                acc[i][3] = fmaf(a, b.w, acc[i][3]);
            }
        }
        __syncthreads();
    }
    {
        const float4 bv = *(const float4*)(bb + c0);
#pragma unroll
        for (int i = 0; i < 8; i++) {
            float4 o;
            o.x = acc[i][0] + bv.x;
            o.y = acc[i][1] + bv.y;
            o.z = acc[i][2] + bv.z;
            o.w = acc[i][3] + bv.w;
            *(float4*)(out + (size_t)(row0 + r0 + i) * 128 + c0) = o;
        }
    }
}
#define GIN_SMEM (9216 + 16384 + 33792)

// ---------------- edge vector scatter-add (4 edges / warp, MLP=4) ---------
#define SCAT_EPW 4
__global__ void scatter_kernel(const float* __restrict__ x, const int* __restrict__ src,
                               const int* __restrict__ dst,
                               const unsigned char* __restrict__ mask,
                               float* __restrict__ agg, int nE) {
    const int w = (blockIdx.x * blockDim.x + threadIdx.x) >> 5;
    const int lane = threadIdx.x & 31;
    const int e0 = w * SCAT_EPW;
    if (e0 >= nE) return;
    float4 v[SCAT_EPW];
    int d[SCAT_EPW];
    bool ok[SCAT_EPW];
#pragma unroll
    for (int i = 0; i < SCAT_EPW; i++) {
        const int e = e0 + i;
        ok[i] = (e < nE) && (!mask || mask[e]);
        if (ok[i]) {
            const int s = src[e];
            d[i] = dst[e];
            v[i] = *(const float4*)(x + (size_t)s * CC_ + lane * 4);
        }
    }
#pragma unroll
    for (int i = 0; i < SCAT_EPW; i++)
        if (ok[i])
            atomicAdd((float4*)(agg + (size_t)d[i] * CC_ + lane * 4), v[i]);
}

// ---------------- scalar edge scatter-add for scores (4 edges / thread) ---
__global__ void scatter_scalar_kernel(const float* __restrict__ srel,
                                      const int* __restrict__ src,
                                      const int* __restrict__ dst,
                                      const unsigned char* __restrict__ mask,
                                      float* __restrict__ ssum, int nE) {
    const int t = blockIdx.x * blockDim.x + threadIdx.x;
    const int e0 = t * 4;
    if (e0 >= nE) return;
    const int4 s4 = *(const int4*)(src + e0);
    const int4 d4 = *(const int4*)(dst + e0);
    bool m0 = true, m1 = true, m2 = true, m3 = true;
    if (mask) {
        m0 = mask[e0]; m1 = mask[e0 + 1]; m2 = mask[e0 + 2]; m3 = mask[e0 + 3];
    }
    float a0 = 0.f, a1 = 0.f, a2 = 0.f, a3 = 0.f;
    if (m0) a0 = srel[s4.x];
    if (m1) a1 = srel[s4.y];
    if (m2) a2 = srel[s4.z];
    if (m3) a3 = srel[s4.w];
    if (m0) atomicAdd(&ssum[d4.x], a0);
    if (m1) atomicAdd(&ssum[d4.y], a1);
    if (m2) atomicAdd(&ssum[d4.z], a2);
    if (m3) atomicAdd(&ssum[d4.w], a3);
}

// ---------------- score pre-pass: srel/sroot dots, zero ssum --------------
__global__ void score_pre_kernel(const float* __restrict__ x,
                                 const float* __restrict__ Wrel,
                                 const float* __restrict__ Wroot,
                                 float* __restrict__ srel, float* __restrict__ sroot,
                                 float* __restrict__ ssum, int n) {
    const int node = blockIdx.x * blockDim.x + threadIdx.x;
    if (node >= n) return;
    const float* xx = x + (size_t)node * CC_;
    float t1 = 0.f, t2 = 0.f;
#pragma unroll 16
    for (int c = 0; c < CC_; ++c) t1 = fmaf(xx[c], Wrel[c], t1);
#pragma unroll 16
    for (int c = 0; c < CC_; ++c) t2 = fmaf(xx[c], Wroot[c], t2);
    srel[node] = t1;
    sroot[node] = t2;
    ssum[node] = 0.f;
}

// ---------------- score finalize + composite sort key + inits -------------
__global__ void score_fin_kernel(const float* __restrict__ ssum,
                                 const float* __restrict__ sroot,
                                 const float* __restrict__ brel,
                                 float* __restrict__ scores,
                                 unsigned long long* __restrict__ key64,
                                 int* __restrict__ iota,
                                 int* __restrict__ newid_init,
                                 float* __restrict__ ozero,
                                 int npg, int n) {
    const int node = blockIdx.x * blockDim.x + threadIdx.x;
    if (node >= n) return;
    const float sc = xla_tanh((ssum[node] + brel[0]) + sroot[node]);
    scores[node] = sc;
    unsigned int u = __float_as_uint(sc);
    unsigned int e = (u & 0x80000000u) ? ~u : (u | 0x80000000u); // ascending encode
    unsigned int kd = ~e;                                         // descending
    const unsigned int g = (unsigned int)(node / npg);
    key64[node] = ((unsigned long long)g << 32) | (unsigned long long)kd;
    iota[node] = node;
    if (newid_init) newid_init[node] = -1;
    if (ozero && node < BGR_ * CC_) ozero[node] = 0.f;
}

// ---------------- selection/gather after sort (1 warp / kept node) -------
__global__ void select_kernel(const float* __restrict__ scores, const int* __restrict__ sidx,
                              const float* __restrict__ xin, float* __restrict__ xout,
                              float* __restrict__ xout2,
                              int* __restrict__ newid, int npg, int k) {
    const int j = blockIdx.x * 8 + (threadIdx.x >> 5);
    if (j >= BGR_ * k) return;
    const int g = j / k, jj = j - g * k;
    const int srcpos = g * npg + jj;
    const int orig = sidx[srcpos];
    const float val = scores[orig];
    const int lane = threadIdx.x & 31;
    float4 v = *(const float4*)(xin + (size_t)orig * CC_ + lane * 4);
    v.x *= val; v.y *= val; v.z *= val; v.w *= val;
    const size_t off = (size_t)j * CC_ + lane * 4;
    *(float4*)(xout + off) = v;
    if (xout2) *(float4*)(xout2 + off) = v;
    if (lane == 0) newid[orig] = j;
}

// ---------------- edge remap after pooling ----------------
__global__ void remap_kernel(const int* __restrict__ src, const int* __restrict__ dst,
                             const int* __restrict__ newid,
                             int* __restrict__ src2, int* __restrict__ dst2,
                             unsigned char* __restrict__ mask2) {
    const int e = blockIdx.x * blockDim.x + threadIdx.x;
    if (e >= EDG_) return;
    const int s = newid[src[e]];
    const int d = newid[dst[e]];
    const bool ok = (s >= 0) && (d >= 0);
    src2[e] = s; dst2[e] = d; mask2[e] = ok ? 1 : 0;
}

// ---------------- per-graph mean pooling: parallel partial sums ----------
#define MEAN_BPG 16
__global__ void mean_part_kernel(const float* __restrict__ x, float* __restrict__ out, int k) {
    const int b = blockIdx.x / MEAN_BPG;
    const int chunk = blockIdx.x % MEAN_BPG;
    const int rows = (k + MEAN_BPG - 1) / MEAN_BPG;
    const int r0 = chunk * rows;
    const int r1 = (r0 + rows < k) ? (r0 + rows) : k;
    const int col = threadIdx.x;  // 0..127
    float s = 0.f;
    for (int r = r0; r < r1; ++r)
        s += x[((size_t)b * k + r) * CC_ + col];
    atomicAdd(&out[b * CC_ + col], s);
}

// ---------------- final MLP head (single block) ----------------
__global__ void head_kernel(const float* __restrict__ out1, const float* __restrict__ out2,
                            const float* __restrict__ Wg, const float* __restrict__ bg,
                            const float* __restrict__ Wr1, const float* __restrict__ br1,
                            const float* __restrict__ gg1, const float* __restrict__ be1,
                            const float* __restrict__ Wr2, const float* __restrict__ br2,
                            const float* __restrict__ gg2, const float* __restrict__ be2,
                            const float* __restrict__ Wout, float* __restrict__ out) {
    __shared__ float cat[8][256];
    __shared__ float gmat[8][128];
    __shared__ float r1[8][64];
    __shared__ float r2[8][32];
    const int tid = threadIdx.x;  // 256 threads
    for (int i = tid; i < 8 * 128; i += 256) {
        const int b = i >> 7, c = i & 127;
        cat[b][c]       = out1[i] / (float)KK1_;
        cat[b][c + 128] = out2[i] / (float)KK2_;
    }
    __syncthreads();
    const float inv = 1.0f / sqrtf(1.0f + 1e-5f);
    if (tid < 128) {
        for (int b = 0; b < 8; b++) {
            float s = 0.f;
            for (int k = 0; k < 256; k++) s = fmaf(cat[b][k], Wg[k * 128 + tid], s);
            gmat[b][tid] = s + bg[tid];
        }
    }
    __syncthreads();
    if (tid < 64) {
        for (int b = 0; b < 8; b++) {
            float s = 0.f;
            for (int k = 0; k < 128; k++) s = fmaf(gmat[b][k], Wr1[k * 64 + tid], s);
            s = (s + br1[tid]) * inv * gg1[tid] + be1[tid];
            r1[b][tid] = fmaxf(s, 0.f);
        }
    }
    __syncthreads();
    if (tid < 32) {
        for (int b = 0; b < 8; b++) {
            float s = 0.f;
            for (int k = 0; k < 64; k++) s = fmaf(r1[b][k], Wr2[k * 32 + tid], s);
            s = (s + br2[tid]) * inv * gg2[tid] + be2[tid];
            r2[b][tid] = fmaxf(s, 0.f);
        }
    }
    __syncthreads();
    if (tid < 32) {
        const int b = tid >> 2, j = tid & 3;
        float s = 0.f;
        for (int k = 0; k < 32; k++) s = fmaf(r2[b][k], Wout[k * 4 + j], s);
        out[b * 4 + j] = s;
    }
}

// ---------------- host orchestration ----------------
extern "C" void kernel_launch(void* const* d_in, const int* in_sizes, int n_in,
                              void* d_out, int out_size) {
    const float* x    = (const float*)d_in[0];
    const int*   ei   = (const int*)d_in[1];
    const int*   src  = ei;
    const int*   dst  = ei + EDG_;
    const float* W0   = (const float*)d_in[3];
    const float* b0   = (const float*)d_in[4];
    const float* W1a  = (const float*)d_in[5];
    const float* b1a  = (const float*)d_in[6];
    const float* W1b  = (const float*)d_in[7];
    const float* b1b  = (const float*)d_in[8];
    const float* Wrel1  = (const float*)d_in[9];
    const float* brel1  = (const float*)d_in[10];
    const float* Wroot1 = (const float*)d_in[11];
    const float* W2a  = (const float*)d_in[12];
    const float* b2a  = (const float*)d_in[13];
    const float* W2b  = (const float*)d_in[14];
    const float* b2b  = (const float*)d_in[15];
    const float* Wrel2  = (const float*)d_in[16];
    const float* brel2  = (const float*)d_in[17];
    const float* Wroot2 = (const float*)d_in[18];
    const float* Wg   = (const float*)d_in[19];
    const float* bg   = (const float*)d_in[20];
    const float* Wr1  = (const float*)d_in[21];
    const float* br1  = (const float*)d_in[22];
    const float* gg1  = (const float*)d_in[23];
    const float* be1  = (const float*)d_in[24];
    const float* Wr2  = (const float*)d_in[25];
    const float* br2  = (const float*)d_in[26];
    const float* gg2  = (const float*)d_in[27];
    const float* be2  = (const float*)d_in[28];
    const float* Wout = (const float*)d_in[29];

    float *bufA, *bufB, *bufC, *scores, *srel, *sroot, *ssum, *o1, *o2;
    unsigned long long *key64, *key64B;
    int *iota, *sidx, *newid, *src2, *dst2;
    unsigned char *mask2, *cubtmp;
    cudaGetSymbolAddress((void**)&bufA, g_bufA);
    cudaGetSymbolAddress((void**)&bufB, g_bufB);
    cudaGetSymbolAddress((void**)&bufC, g_bufC);
    cudaGetSymbolAddress((void**)&scores, g_scores);
    cudaGetSymbolAddress((void**)&srel, g_srel);
    cudaGetSymbolAddress((void**)&sroot, g_sroot);
    cudaGetSymbolAddress((void**)&ssum, g_ssum);
    cudaGetSymbolAddress((void**)&key64, g_key64);
    cudaGetSymbolAddress((void**)&key64B, g_key64B);
    cudaGetSymbolAddress((void**)&iota, g_iota);
    cudaGetSymbolAddress((void**)&sidx, g_sidx);
    cudaGetSymbolAddress((void**)&newid, g_newid);
    cudaGetSymbolAddress((void**)&src2, g_src2);
    cudaGetSymbolAddress((void**)&dst2, g_dst2);
    cudaGetSymbolAddress((void**)&mask2, g_mask2);
    cudaGetSymbolAddress((void**)&o1, g_out1);
    cudaGetSymbolAddress((void**)&o2, g_out2);
    cudaGetSymbolAddress((void**)&cubtmp, g_cubtmp);

    cudaFuncSetAttribute(gin_kernel, cudaFuncAttributeMaxDynamicSharedMemorySize, GIN_SMEM);

    const int scat_blocks = (EDG_ + SCAT_EPW * 8 - 1) / (SCAT_EPW * 8);

    // ---- stage 0: h0 = relu(x @ W0 + b0) -> bufA AND bufB (scatter base)
    gemm_kernel<FF_, true, true><<<NB_ / 64, 256>>>(x, W0, b0, bufA, bufB);

    // ---- GIN layer 1: bufB += segsum(h0) ; h1 = gin(bufB)
    scatter_kernel<<<scat_blocks, 256>>>(bufA, src, dst, nullptr, bufB, EDG_);
    gin_kernel<<<NB_ / 64, 256, GIN_SMEM>>>(bufB, W1a, b1a, W1b, b1b, bufB);  // h1 = bufB

    // ---- SAGPool 1
    score_pre_kernel<<<(NB_ + 255) / 256, 256>>>(bufB, Wrel1, Wroot1, srel, sroot, ssum, NB_);
    scatter_scalar_kernel<<<(EDG_ / 4 + 255) / 256, 256>>>(srel, src, dst, nullptr, ssum, EDG_);
    score_fin_kernel<<<(NB_ + 255) / 256, 256>>>(ssum, sroot, brel1, scores, key64, iota,
                                                 newid, o1, NPG_, NB_);
    {
        size_t tmp = 0;
        cub::DeviceRadixSort::SortPairs(nullptr, tmp, key64, key64B, iota, sidx, NB_, 0, 35);
        if (tmp > sizeof(g_cubtmp)) tmp = sizeof(g_cubtmp);
        cub::DeviceRadixSort::SortPairs((void*)cubtmp, tmp, key64, key64B, iota, sidx, NB_, 0, 35);
    }
    // h2 -> bufC AND bufA (layer-2 scatter base)
    select_kernel<<<NB1_ / 8, 256>>>(scores, sidx, bufB, bufC, bufA, newid, NPG_, KK1_);
    mean_part_kernel<<<BGR_ * MEAN_BPG, 128>>>(bufC, o1, KK1_);
    remap_kernel<<<EDG_ / 256, 256>>>(src, dst, newid, src2, dst2, mask2);

    // ---- GIN layer 2: bufA += segsum(h2) ; h3 = gin(bufA)
    scatter_kernel<<<scat_blocks, 256>>>(bufC, src2, dst2, mask2, bufA, EDG_);
    gin_kernel<<<NB1_ / 64, 256, GIN_SMEM>>>(bufA, W2a, b2a, W2b, b2b, bufC);  // h3 = bufC

    // ---- SAGPool 2
    score_pre_kernel<<<(NB1_ + 255) / 256, 256>>>(bufC, Wrel2, Wroot2, srel, sroot, ssum, NB1_);
    scatter_scalar_kernel<<<(EDG_ / 4 + 255) / 256, 256>>>(srel, src2, dst2, mask2, ssum, EDG_);
    score_fin_kernel<<<(NB1_ + 255) / 256, 256>>>(ssum, sroot, brel2, scores, key64, iota,
                                                  nullptr, o2, KK1_, NB1_);
    {
        size_t tmp = 0;
        cub::DeviceRadixSort::SortPairs(nullptr, tmp, key64, key64B, iota, sidx, NB1_, 0, 35);
        if (tmp > sizeof(g_cubtmp)) tmp = sizeof(g_cubtmp);
        cub::DeviceRadixSort::SortPairs((void*)cubtmp, tmp, key64, key64B, iota, sidx, NB1_, 0, 35);
    }
    select_kernel<<<NB2_ / 8, 256>>>(scores, sidx, bufC, bufB, nullptr, newid, KK1_, KK2_);
    mean_part_kernel<<<BGR_ * MEAN_BPG, 128>>>(bufB, o2, KK2_);

    // ---- head
    head_kernel<<<1, 256>>>(o1, o2, Wg, bg, Wr1, br1, gg1, be1,
                            Wr2, br2, gg2, be2, Wout, (float*)d_out);
}

// round 11
// speedup vs baseline: 1.8245x; 1.2339x over previous
#include <cuda_runtime.h>
#include <cub/cub.cuh>

// Problem constants
#define NB_   80000      // B*N nodes layer 0/1
#define BGR_  8          // graphs
#define NPG_  10000      // nodes per graph (layer 1)
#define EDG_  640000     // edges
#define CC_   128        // channels
#define FF_   64         // input features
#define KK1_  6000       // kept after pool1 (per graph)
#define NB1_  48000      // B*KK1
#define KK2_  3600       // kept after pool2 (per graph)
#define NB2_  28800      // B*KK2

// ---------------- static device scratch (no allocs allowed) ----------------
__device__ float g_bufA[NB_ * CC_];
__device__ float g_bufB[NB_ * CC_];
__device__ float g_bufC[NB_ * CC_];
__device__ float g_scores[NB_];
__device__ float g_srel[NB_];
__device__ float g_sroot[NB_];
__device__ float g_ssum[NB_];
__device__ unsigned long long g_key64[NB_];
__device__ unsigned long long g_key64B[NB_];
__device__ int   g_iota[NB_];
__device__ int   g_sidx[NB_];
__device__ int   g_newid[NB_];
__device__ int   g_src2[EDG_];
__device__ int   g_dst2[EDG_];
__device__ unsigned char g_mask2[EDG_];
__device__ float g_out1[BGR_ * CC_];
__device__ float g_out2[BGR_ * CC_];
__device__ unsigned char g_cubtmp[1u << 24];  // 16 MB cub temp

// ---------------- XLA-GPU (MLIR math polynomial approximation) tanh -------
__device__ __forceinline__ float xla_tanh(float ax) {
    const float plus_clamp  = 7.99881172180175781f;
    const float minus_clamp = -7.99881172180175781f;
    const float tiny = 0.0004f;
    const float alpha_1  = 4.89352455891786e-03f;
    const float alpha_3  = 6.37261928875436e-04f;
    const float alpha_5  = 1.48572235717979e-05f;
    const float alpha_7  = 5.12229709037114e-08f;
    const float alpha_9  = -8.60467152213735e-11f;
    const float alpha_11 = 2.00018790482477e-13f;
    const float alpha_13 = -2.76076847742355e-16f;
    const float beta_0 = 4.89352518554385e-03f;
    const float beta_2 = 2.26843463243900e-03f;
    const float beta_4 = 1.18534705686654e-04f;
    const float beta_6 = 1.19825839466702e-06f;

    float x = fminf(fmaxf(ax, minus_clamp), plus_clamp);
    float x2 = x * x;
    float p = fmaf(x2, alpha_13, alpha_11);
    p = fmaf(x2, p, alpha_9);
    p = fmaf(x2, p, alpha_7);
    p = fmaf(x2, p, alpha_5);
    p = fmaf(x2, p, alpha_3);
    p = fmaf(x2, p, alpha_1);
    p = x * p;
    float q = fmaf(x2, beta_6, beta_4);
    q = fmaf(x2, q, beta_2);
    q = fmaf(x2, q, beta_0);
    float r = p / q;
    return (fabsf(ax) < tiny) ? ax : r;
}

// ---------------- GEMM (stage 0): [M x K] @ [K x 128] + bias + relu -------
template <int K, bool RELU, bool DUAL>
__global__ void __launch_bounds__(256) gemm_kernel(const float* __restrict__ A,
                                                   const float* __restrict__ W,
                                                   const float* __restrict__ bias,
                                                   float* __restrict__ out,
                                                   float* __restrict__ out2) {
    __shared__ float As[64][36];
    __shared__ float Bs[32][128];

    const int tid  = threadIdx.x;
    const int row0 = blockIdx.x * 64;
    const int warp = tid >> 5, lane = tid & 31;
    const int r0 = warp * 8;
    const int c0 = lane * 4;

    float acc[8][4];
#pragma unroll
    for (int i = 0; i < 8; i++)
#pragma unroll
        for (int j = 0; j < 4; j++) acc[i][j] = 0.f;

    for (int k0 = 0; k0 < K; k0 += 32) {
        {
            const int r  = tid >> 3;
            const int k4 = (tid & 7) * 4;
            float4 v0 = *(const float4*)(A + (size_t)(row0 + r) * K + k0 + k4);
            float4 v1 = *(const float4*)(A + (size_t)(row0 + r + 32) * K + k0 + k4);
            *(float4*)&As[r][k4]      = v0;
            *(float4*)&As[r + 32][k4] = v1;
        }
#pragma unroll
        for (int it = 0; it < 4; ++it) {
            const int f  = tid + it * 256;
            const int k  = f >> 5;
            const int c4 = (f & 31) * 4;
            *(float4*)&Bs[k][c4] = *(const float4*)(W + (size_t)(k0 + k) * 128 + c4);
        }
        __syncthreads();
#pragma unroll
        for (int kk = 0; kk < 32; ++kk) {
            const float4 b = *(const float4*)&Bs[kk][c0];
#pragma unroll
            for (int i = 0; i < 8; i++) {
                const float a = As[r0 + i][kk];
                acc[i][0] = fmaf(a, b.x, acc[i][0]);
                acc[i][1] = fmaf(a, b.y, acc[i][1]);
                acc[i][2] = fmaf(a, b.z, acc[i][2]);
                acc[i][3] = fmaf(a, b.w, acc[i][3]);
            }
        }
        __syncthreads();
    }

    const float4 bv = *(const float4*)(bias + c0);
#pragma unroll
    for (int i = 0; i < 8; i++) {
        float4 o;
        o.x = acc[i][0] + bv.x;
        o.y = acc[i][1] + bv.y;
        o.z = acc[i][2] + bv.z;
        o.w = acc[i][3] + bv.w;
        if (RELU) {
            o.x = fmaxf(o.x, 0.f); o.y = fmaxf(o.y, 0.f);
            o.z = fmaxf(o.z, 0.f); o.w = fmaxf(o.w, 0.f);
        }
        const size_t off = (size_t)(row0 + r0 + i) * 128 + c0;
        *(float4*)(out + off) = o;
        if (DUAL) *(float4*)(out2 + off) = o;
    }
}

// ---------------- fused GIN nn: out = relu(A@Wa+ba) @ Wb + bb -------------
__global__ void __launch_bounds__(256) gin_kernel(const float* __restrict__ A,
                                                  const float* __restrict__ Wa,
                                                  const float* __restrict__ ba,
                                                  const float* __restrict__ Wb,
                                                  const float* __restrict__ bb,
                                                  float* __restrict__ out) {
    extern __shared__ char smem[];
    float (*As)[36]  = (float(*)[36])smem;                    //  9216 B
    float (*Bs)[128] = (float(*)[128])(smem + 9216);          // 16384 B
    float (*T1)[132] = (float(*)[132])(smem + 9216 + 16384);  // 33792 B

    const int tid  = threadIdx.x;
    const int row0 = blockIdx.x * 64;
    const int warp = tid >> 5, lane = tid & 31;
    const int r0 = warp * 8;
    const int c0 = lane * 4;

    float acc[8][4];
#pragma unroll
    for (int i = 0; i < 8; i++)
#pragma unroll
        for (int j = 0; j < 4; j++) acc[i][j] = 0.f;

    // ---- phase 1: t1 = relu(A@Wa + ba)
    for (int k0 = 0; k0 < CC_; k0 += 32) {
        {
            const int r  = tid >> 3;
            const int k4 = (tid & 7) * 4;
            float4 v0 = *(const float4*)(A + (size_t)(row0 + r) * CC_ + k0 + k4);
            float4 v1 = *(const float4*)(A + (size_t)(row0 + r + 32) * CC_ + k0 + k4);
            *(float4*)&As[r][k4]      = v0;
            *(float4*)&As[r + 32][k4] = v1;
        }
#pragma unroll
        for (int it = 0; it < 4; ++it) {
            const int f  = tid + it * 256;
            const int k  = f >> 5;
            const int c4 = (f & 31) * 4;
            *(float4*)&Bs[k][c4] = *(const float4*)(Wa + (size_t)(k0 + k) * 128 + c4);
        }
        __syncthreads();
#pragma unroll
        for (int kk = 0; kk < 32; ++kk) {
            const float4 b = *(const float4*)&Bs[kk][c0];
#pragma unroll
            for (int i = 0; i < 8; i++) {
                const float a = As[r0 + i][kk];
                acc[i][0] = fmaf(a, b.x, acc[i][0]);
                acc[i][1] = fmaf(a, b.y, acc[i][1]);
                acc[i][2] = fmaf(a, b.z, acc[i][2]);
                acc[i][3] = fmaf(a, b.w, acc[i][3]);
            }
        }
        __syncthreads();
    }
    {
        const float4 bv = *(const float4*)(ba + c0);
#pragma unroll
        for (int i = 0; i < 8; i++) {
            float4 o;
            o.x = fmaxf(acc[i][0] + bv.x, 0.f);
            o.y = fmaxf(acc[i][1] + bv.y, 0.f);
            o.z = fmaxf(acc[i][2] + bv.z, 0.f);
            o.w = fmaxf(acc[i][3] + bv.w, 0.f);
            *(float4*)&T1[r0 + i][c0] = o;
        }
    }

    // ---- phase 2: out = t1 @ Wb + bb
#pragma unroll
    for (int i = 0; i < 8; i++)
#pragma unroll
        for (int j = 0; j < 4; j++) acc[i][j] = 0.f;

    for (int k0 = 0; k0 < CC_; k0 += 32) {
#pragma unroll
        for (int it = 0; it < 4; ++it) {
            const int f  = tid + it * 256;
            const int k  = f >> 5;
            const int c4 = (f & 31) * 4;
            *(float4*)&Bs[k][c4] = *(const float4*)(Wb + (size_t)(k0 + k) * 128 + c4);
        }
        __syncthreads();   // also orders T1 writes before T1 reads (k0 == 0)
#pragma unroll
        for (int kk = 0; kk < 32; ++kk) {
            const float4 b = *(const float4*)&Bs[kk][c0];
#pragma unroll
            for (int i = 0; i < 8; i++) {
                const float a = T1[r0 + i][k0 + kk];
                acc[i][0] = fmaf(a, b.x, acc[i][0]);
                acc[i][1] = fmaf(a, b.y, acc[i][1]);
                acc[i][2] = fmaf(a, b.z, acc[i][2]);
                acc[i][3] = fmaf(a, b.w, acc[i][3]);
            }
        }
        __syncthreads();
    }
    {
        const float4 bv = *(const float4*)(bb + c0);
#pragma unroll
        for (int i = 0; i < 8; i++) {
            float4 o;
            o.x = acc[i][0] + bv.x;
            o.y = acc[i][1] + bv.y;
            o.z = acc[i][2] + bv.z;
            o.w = acc[i][3] + bv.w;
            *(float4*)(out + (size_t)(row0 + r0 + i) * 128 + c0) = o;
        }
    }
}
#define GIN_SMEM (9216 + 16384 + 33792)

// ---------------- edge vector scatter-add (4 edges / warp, MLP=4) ---------
#define SCAT_EPW 4
__global__ void scatter_kernel(const float* __restrict__ x, const int* __restrict__ src,
                               const int* __restrict__ dst,
                               const unsigned char* __restrict__ mask,
                               float* __restrict__ agg, int nE) {
    const int w = (blockIdx.x * blockDim.x + threadIdx.x) >> 5;
    const int lane = threadIdx.x & 31;
    const int e0 = w * SCAT_EPW;
    if (e0 >= nE) return;
    float4 v[SCAT_EPW];
    int d[SCAT_EPW];
    bool ok[SCAT_EPW];
#pragma unroll
    for (int i = 0; i < SCAT_EPW; i++) {
        const int e = e0 + i;
        ok[i] = (e < nE) && (!mask || mask[e]);
        if (ok[i]) {
            const int s = src[e];
            d[i] = dst[e];
            v[i] = *(const float4*)(x + (size_t)s * CC_ + lane * 4);
        }
    }
#pragma unroll
    for (int i = 0; i < SCAT_EPW; i++)
        if (ok[i])
            atomicAdd((float4*)(agg + (size_t)d[i] * CC_ + lane * 4), v[i]);
}

// ---------------- scalar edge scatter-add for scores (4 edges / thread) ---
__global__ void scatter_scalar_kernel(const float* __restrict__ srel,
                                      const int* __restrict__ src,
                                      const int* __restrict__ dst,
                                      const unsigned char* __restrict__ mask,
                                      float* __restrict__ ssum, int nE) {
    const int t = blockIdx.x * blockDim.x + threadIdx.x;
    const int e0 = t * 4;
    if (e0 >= nE) return;
    const int4 s4 = *(const int4*)(src + e0);
    const int4 d4 = *(const int4*)(dst + e0);
    bool m0 = true, m1 = true, m2 = true, m3 = true;
    if (mask) {
        m0 = mask[e0]; m1 = mask[e0 + 1]; m2 = mask[e0 + 2]; m3 = mask[e0 + 3];
    }
    float a0 = 0.f, a1 = 0.f, a2 = 0.f, a3 = 0.f;
    if (m0) a0 = srel[s4.x];
    if (m1) a1 = srel[s4.y];
    if (m2) a2 = srel[s4.z];
    if (m3) a3 = srel[s4.w];
    if (m0) atomicAdd(&ssum[d4.x], a0);
    if (m1) atomicAdd(&ssum[d4.y], a1);
    if (m2) atomicAdd(&ssum[d4.z], a2);
    if (m3) atomicAdd(&ssum[d4.w], a3);
}

// ---------------- score pre-pass: warp-per-node coalesced dots ------------
// Lane l handles channels [4l, 4l+4); butterfly-shuffle reduce t1, t2.
__global__ void score_pre_kernel(const float* __restrict__ x,
                                 const float* __restrict__ Wrel,
                                 const float* __restrict__ Wroot,
                                 float* __restrict__ srel, float* __restrict__ sroot,
                                 float* __restrict__ ssum, int n) {
    const int node = (blockIdx.x * blockDim.x + threadIdx.x) >> 5;
    if (node >= n) return;
    const int lane = threadIdx.x & 31;
    const float4 xv = *(const float4*)(x + (size_t)node * CC_ + lane * 4);
    const float4 wr = *(const float4*)(Wrel + lane * 4);
    const float4 wt = *(const float4*)(Wroot + lane * 4);
    float t1 = xv.x * wr.x + xv.y * wr.y + xv.z * wr.z + xv.w * wr.w;
    float t2 = xv.x * wt.x + xv.y * wt.y + xv.z * wt.z + xv.w * wt.w;
#pragma unroll
    for (int o = 16; o > 0; o >>= 1) {
        t1 += __shfl_xor_sync(0xffffffffu, t1, o);
        t2 += __shfl_xor_sync(0xffffffffu, t2, o);
    }
    if (lane == 0) {
        srel[node] = t1;
        sroot[node] = t2;
        ssum[node] = 0.f;
    }
}

// ---------------- score finalize + composite sort key + inits -------------
__global__ void score_fin_kernel(const float* __restrict__ ssum,
                                 const float* __restrict__ sroot,
                                 const float* __restrict__ brel,
                                 float* __restrict__ scores,
                                 unsigned long long* __restrict__ key64,
                                 int* __restrict__ iota,
                                 int* __restrict__ newid_init,
                                 float* __restrict__ ozero,
                                 int npg, int n) {
    const int node = blockIdx.x * blockDim.x + threadIdx.x;
    if (node >= n) return;
    const float sc = xla_tanh((ssum[node] + brel[0]) + sroot[node]);
    scores[node] = sc;
    unsigned int u = __float_as_uint(sc);
    unsigned int e = (u & 0x80000000u) ? ~u : (u | 0x80000000u); // ascending encode
    unsigned int kd = ~e;                                         // descending
    const unsigned int g = (unsigned int)(node / npg);
    key64[node] = ((unsigned long long)g << 32) | (unsigned long long)kd;
    iota[node] = node;
    if (newid_init) newid_init[node] = -1;
    if (ozero && node < BGR_ * CC_) ozero[node] = 0.f;
}

// ---------------- selection/gather after sort (1 warp / kept node) -------
__global__ void select_kernel(const float* __restrict__ scores, const int* __restrict__ sidx,
                              const float* __restrict__ xin, float* __restrict__ xout,
                              float* __restrict__ xout2,
                              int* __restrict__ newid, int npg, int k) {
    const int j = blockIdx.x * 8 + (threadIdx.x >> 5);
    if (j >= BGR_ * k) return;
    const int g = j / k, jj = j - g * k;
    const int srcpos = g * npg + jj;
    const int orig = sidx[srcpos];
    const float val = scores[orig];
    const int lane = threadIdx.x & 31;
    float4 v = *(const float4*)(xin + (size_t)orig * CC_ + lane * 4);
    v.x *= val; v.y *= val; v.z *= val; v.w *= val;
    const size_t off = (size_t)j * CC_ + lane * 4;
    *(float4*)(xout + off) = v;
    if (xout2) *(float4*)(xout2 + off) = v;
    if (lane == 0) newid[orig] = j;
}

// ---------------- edge remap after pooling ----------------
__global__ void remap_kernel(const int* __restrict__ src, const int* __restrict__ dst,
                             const int* __restrict__ newid,
                             int* __restrict__ src2, int* __restrict__ dst2,
                             unsigned char* __restrict__ mask2) {
    const int e = blockIdx.x * blockDim.x + threadIdx.x;
    if (e >= EDG_) return;
    const int s = newid[src[e]];
    const int d = newid[dst[e]];
    const bool ok = (s >= 0) && (d >= 0);
    src2[e] = s; dst2[e] = d; mask2[e] = ok ? 1 : 0;
}

// ---------------- per-graph mean pooling: parallel partial sums ----------
#define MEAN_BPG 16
__global__ void mean_part_kernel(const float* __restrict__ x, float* __restrict__ out, int k) {
    const int b = blockIdx.x / MEAN_BPG;
    const int chunk = blockIdx.x % MEAN_BPG;
    const int rows = (k + MEAN_BPG - 1) / MEAN_BPG;
    const int r0 = chunk * rows;
    const int r1 = (r0 + rows < k) ? (r0 + rows) : k;
    const int col = threadIdx.x;  // 0..127
    float s = 0.f;
    for (int r = r0; r < r1; ++r)
        s += x[((size_t)b * k + r) * CC_ + col];
    atomicAdd(&out[b * CC_ + col], s);
}

// ---------------- final MLP head (single block) ----------------
__global__ void head_kernel(const float* __restrict__ out1, const float* __restrict__ out2,
                            const float* __restrict__ Wg, const float* __restrict__ bg,
                            const float* __restrict__ Wr1, const float* __restrict__ br1,
                            const float* __restrict__ gg1, const float* __restrict__ be1,
                            const float* __restrict__ Wr2, const float* __restrict__ br2,
                            const float* __restrict__ gg2, const float* __restrict__ be2,
                            const float* __restrict__ Wout, float* __restrict__ out) {
    __shared__ float cat[8][256];
    __shared__ float gmat[8][128];
    __shared__ float r1[8][64];
    __shared__ float r2[8][32];
    const int tid = threadIdx.x;  // 256 threads
    for (int i = tid; i < 8 * 128; i += 256) {
        const int b = i >> 7, c = i & 127;
        cat[b][c]       = out1[i] / (float)KK1_;
        cat[b][c + 128] = out2[i] / (float)KK2_;
    }
    __syncthreads();
    const float inv = 1.0f / sqrtf(1.0f + 1e-5f);
    if (tid < 128) {
        for (int b = 0; b < 8; b++) {
            float s = 0.f;
            for (int k = 0; k < 256; k++) s = fmaf(cat[b][k], Wg[k * 128 + tid], s);
            gmat[b][tid] = s + bg[tid];
        }
    }
    __syncthreads();
    if (tid < 64) {
        for (int b = 0; b < 8; b++) {
            float s = 0.f;
            for (int k = 0; k < 128; k++) s = fmaf(gmat[b][k], Wr1[k * 64 + tid], s);
            s = (s + br1[tid]) * inv * gg1[tid] + be1[tid];
            r1[b][tid] = fmaxf(s, 0.f);
        }
    }
    __syncthreads();
    if (tid < 32) {
        for (int b = 0; b < 8; b++) {
            float s = 0.f;
            for (int k = 0; k < 64; k++) s = fmaf(r1[b][k], Wr2[k * 32 + tid], s);
            s = (s + br2[tid]) * inv * gg2[tid] + be2[tid];
            r2[b][tid] = fmaxf(s, 0.f);
        }
    }
    __syncthreads();
    if (tid < 32) {
        const int b = tid >> 2, j = tid & 3;
        float s = 0.f;
        for (int k = 0; k < 32; k++) s = fmaf(r2[b][k], Wout[k * 4 + j], s);
        out[b * 4 + j] = s;
    }
}

// ---------------- host orchestration ----------------
extern "C" void kernel_launch(void* const* d_in, const int* in_sizes, int n_in,
                              void* d_out, int out_size) {
    const float* x    = (const float*)d_in[0];
    const int*   ei   = (const int*)d_in[1];
    const int*   src  = ei;
    const int*   dst  = ei + EDG_;
    const float* W0   = (const float*)d_in[3];
    const float* b0   = (const float*)d_in[4];
    const float* W1a  = (const float*)d_in[5];
    const float* b1a  = (const float*)d_in[6];
    const float* W1b  = (const float*)d_in[7];
    const float* b1b  = (const float*)d_in[8];
    const float* Wrel1  = (const float*)d_in[9];
    const float* brel1  = (const float*)d_in[10];
    const float* Wroot1 = (const float*)d_in[11];
    const float* W2a  = (const float*)d_in[12];
    const float* b2a  = (const float*)d_in[13];
    const float* W2b  = (const float*)d_in[14];
    const float* b2b  = (const float*)d_in[15];
    const float* Wrel2  = (const float*)d_in[16];
    const float* brel2  = (const float*)d_in[17];
    const float* Wroot2 = (const float*)d_in[18];
    const float* Wg   = (const float*)d_in[19];
    const float* bg   = (const float*)d_in[20];
    const float* Wr1  = (const float*)d_in[21];
    const float* br1  = (const float*)d_in[22];
    const float* gg1  = (const float*)d_in[23];
    const float* be1  = (const float*)d_in[24];
    const float* Wr2  = (const float*)d_in[25];
    const float* br2  = (const float*)d_in[26];
    const float* gg2  = (const float*)d_in[27];
    const float* be2  = (const float*)d_in[28];
    const float* Wout = (const float*)d_in[29];

    float *bufA, *bufB, *bufC, *scores, *srel, *sroot, *ssum, *o1, *o2;
    unsigned long long *key64, *key64B;
    int *iota, *sidx, *newid, *src2, *dst2;
    unsigned char *mask2, *cubtmp;
    cudaGetSymbolAddress((void**)&bufA, g_bufA);
    cudaGetSymbolAddress((void**)&bufB, g_bufB);
    cudaGetSymbolAddress((void**)&bufC, g_bufC);
    cudaGetSymbolAddress((void**)&scores, g_scores);
    cudaGetSymbolAddress((void**)&srel, g_srel);
    cudaGetSymbolAddress((void**)&sroot, g_sroot);
    cudaGetSymbolAddress((void**)&ssum, g_ssum);
    cudaGetSymbolAddress((void**)&key64, g_key64);
    cudaGetSymbolAddress((void**)&key64B, g_key64B);
    cudaGetSymbolAddress((void**)&iota, g_iota);
    cudaGetSymbolAddress((void**)&sidx, g_sidx);
    cudaGetSymbolAddress((void**)&newid, g_newid);
    cudaGetSymbolAddress((void**)&src2, g_src2);
    cudaGetSymbolAddress((void**)&dst2, g_dst2);
    cudaGetSymbolAddress((void**)&mask2, g_mask2);
    cudaGetSymbolAddress((void**)&o1, g_out1);
    cudaGetSymbolAddress((void**)&o2, g_out2);
    cudaGetSymbolAddress((void**)&cubtmp, g_cubtmp);

    cudaFuncSetAttribute(gin_kernel, cudaFuncAttributeMaxDynamicSharedMemorySize, GIN_SMEM);

    const int scat_blocks = (EDG_ + SCAT_EPW * 8 - 1) / (SCAT_EPW * 8);

    // ---- stage 0: h0 = relu(x @ W0 + b0) -> bufA AND bufB (scatter base)
    gemm_kernel<FF_, true, true><<<NB_ / 64, 256>>>(x, W0, b0, bufA, bufB);

    // ---- GIN layer 1: bufB += segsum(h0) ; h1 = gin(bufB)
    scatter_kernel<<<scat_blocks, 256>>>(bufA, src, dst, nullptr, bufB, EDG_);
    gin_kernel<<<NB_ / 64, 256, GIN_SMEM>>>(bufB, W1a, b1a, W1b, b1b, bufB);  // h1 = bufB

    // ---- SAGPool 1
    score_pre_kernel<<<NB_ / 8, 256>>>(bufB, Wrel1, Wroot1, srel, sroot, ssum, NB_);
    scatter_scalar_kernel<<<(EDG_ / 4 + 255) / 256, 256>>>(srel, src, dst, nullptr, ssum, EDG_);
    score_fin_kernel<<<(NB_ + 255) / 256, 256>>>(ssum, sroot, brel1, scores, key64, iota,
                                                 newid, o1, NPG_, NB_);
    {
        size_t tmp = 0;
        cub::DeviceRadixSort::SortPairs(nullptr, tmp, key64, key64B, iota, sidx, NB_, 0, 35);
        if (tmp > sizeof(g_cubtmp)) tmp = sizeof(g_cubtmp);
        cub::DeviceRadixSort::SortPairs((void*)cubtmp, tmp, key64, key64B, iota, sidx, NB_, 0, 35);
    }
    // h2 -> bufC AND bufA (layer-2 scatter base)
    select_kernel<<<NB1_ / 8, 256>>>(scores, sidx, bufB, bufC, bufA, newid, NPG_, KK1_);
    mean_part_kernel<<<BGR_ * MEAN_BPG, 128>>>(bufC, o1, KK1_);
    remap_kernel<<<EDG_ / 256, 256>>>(src, dst, newid, src2, dst2, mask2);

    // ---- GIN layer 2: bufA += segsum(h2) ; h3 = gin(bufA)
    scatter_kernel<<<scat_blocks, 256>>>(bufC, src2, dst2, mask2, bufA, EDG_);
    gin_kernel<<<NB1_ / 64, 256, GIN_SMEM>>>(bufA, W2a, b2a, W2b, b2b, bufC);  // h3 = bufC

    // ---- SAGPool 2
    score_pre_kernel<<<NB1_ / 8, 256>>>(bufC, Wrel2, Wroot2, srel, sroot, ssum, NB1_);
    scatter_scalar_kernel<<<(EDG_ / 4 + 255) / 256, 256>>>(srel, src2, dst2, mask2, ssum, EDG_);
    score_fin_kernel<<<(NB1_ + 255) / 256, 256>>>(ssum, sroot, brel2, scores, key64, iota,
                                                  nullptr, o2, KK1_, NB1_);
    {
        size_t tmp = 0;
        cub::DeviceRadixSort::SortPairs(nullptr, tmp, key64, key64B, iota, sidx, NB1_, 0, 35);
        if (tmp > sizeof(g_cubtmp)) tmp = sizeof(g_cubtmp);
        cub::DeviceRadixSort::SortPairs((void*)cubtmp, tmp, key64, key64B, iota, sidx, NB1_, 0, 35);
    }
    select_kernel<<<NB2_ / 8, 256>>>(scores, sidx, bufC, bufB, nullptr, newid, KK1_, KK2_);
    mean_part_kernel<<<BGR_ * MEAN_BPG, 128>>>(bufB, o2, KK2_);

    // ---- head
    head_kernel<<<1, 256>>>(o1, o2, Wg, bg, Wr1, br1, gg1, be1,
                            Wr2, br2, gg2, be2, Wout, (float*)d_out);
}

// round 14
// speedup vs baseline: 1.8768x; 1.0287x over previous
#include <cuda_runtime.h>
#include <cub/cub.cuh>

// Problem constants
#define NB_   80000      // B*N nodes layer 0/1
#define BGR_  8          // graphs
#define NPG_  10000      // nodes per graph (layer 1)
#define EDG_  640000     // edges
#define CC_   128        // channels
#define FF_   64         // input features
#define KK1_  6000       // kept after pool1 (per graph)
#define NB1_  48000      // B*KK1
#define KK2_  3600       // kept after pool2 (per graph)
#define NB2_  28800      // B*KK2

// ---------------- static device scratch (no allocs allowed) ----------------
__device__ float g_bufA[NB_ * CC_];
__device__ float g_bufB[NB_ * CC_];
__device__ float g_bufC[NB_ * CC_];
__device__ float g_scores[NB_];
__device__ float g_srel[NB_];
__device__ float g_sroot[NB_];
__device__ float g_ssum[NB_];
__device__ unsigned long long g_key64[NB_];
__device__ unsigned long long g_key64B[NB_];
__device__ int   g_iota[NB_];
__device__ int   g_sidx[NB_];
__device__ int   g_newid[NB_];
__device__ float g_out1[BGR_ * CC_];
__device__ float g_out2[BGR_ * CC_];
__device__ unsigned char g_cubtmp[1u << 24];  // 16 MB cub temp

// ---------------- XLA-GPU (MLIR math polynomial approximation) tanh -------
__device__ __forceinline__ float xla_tanh(float ax) {
    const float plus_clamp  = 7.99881172180175781f;
    const float minus_clamp = -7.99881172180175781f;
    const float tiny = 0.0004f;
    const float alpha_1  = 4.89352455891786e-03f;
    const float alpha_3  = 6.37261928875436e-04f;
    const float alpha_5  = 1.48572235717979e-05f;
    const float alpha_7  = 5.12229709037114e-08f;
    const float alpha_9  = -8.60467152213735e-11f;
    const float alpha_11 = 2.00018790482477e-13f;
    const float alpha_13 = -2.76076847742355e-16f;
    const float beta_0 = 4.89352518554385e-03f;
    const float beta_2 = 2.26843463243900e-03f;
    const float beta_4 = 1.18534705686654e-04f;
    const float beta_6 = 1.19825839466702e-06f;

    float x = fminf(fmaxf(ax, minus_clamp), plus_clamp);
    float x2 = x * x;
    float p = fmaf(x2, alpha_13, alpha_11);
    p = fmaf(x2, p, alpha_9);
    p = fmaf(x2, p, alpha_7);
    p = fmaf(x2, p, alpha_5);
    p = fmaf(x2, p, alpha_3);
    p = fmaf(x2, p, alpha_1);
    p = x * p;
    float q = fmaf(x2, beta_6, beta_4);
    q = fmaf(x2, q, beta_2);
    q = fmaf(x2, q, beta_0);
    float r = p / q;
    return (fabsf(ax) < tiny) ? ax : r;
}

// ---------------- GEMM (stage 0): [M x K] @ [K x 128] + bias + relu -------
template <int K, bool RELU, bool DUAL>
__global__ void __launch_bounds__(256) gemm_kernel(const float* __restrict__ A,
                                                   const float* __restrict__ W,
                                                   const float* __restrict__ bias,
                                                   float* __restrict__ out,
                                                   float* __restrict__ out2) {
    __shared__ float As[64][36];
    __shared__ float Bs[32][128];

    const int tid  = threadIdx.x;
    const int row0 = blockIdx.x * 64;
    const int warp = tid >> 5, lane = tid & 31;
    const int r0 = warp * 8;
    const int c0 = lane * 4;

    float acc[8][4];
#pragma unroll
    for (int i = 0; i < 8; i++)
#pragma unroll
        for (int j = 0; j < 4; j++) acc[i][j] = 0.f;

    for (int k0 = 0; k0 < K; k0 += 32) {
        {
            const int r  = tid >> 3;
            const int k4 = (tid & 7) * 4;
            float4 v0 = *(const float4*)(A + (size_t)(row0 + r) * K + k0 + k4);
            float4 v1 = *(const float4*)(A + (size_t)(row0 + r + 32) * K + k0 + k4);
            *(float4*)&As[r][k4]      = v0;
            *(float4*)&As[r + 32][k4] = v1;
        }
#pragma unroll
        for (int it = 0; it < 4; ++it) {
            const int f  = tid + it * 256;
            const int k  = f >> 5;
            const int c4 = (f & 31) * 4;
            *(float4*)&Bs[k][c4] = *(const float4*)(W + (size_t)(k0 + k) * 128 + c4);
        }
        __syncthreads();
#pragma unroll
        for (int kk = 0; kk < 32; ++kk) {
            const float4 b = *(const float4*)&Bs[kk][c0];
#pragma unroll
            for (int i = 0; i < 8; i++) {
                const float a = As[r0 + i][kk];
                acc[i][0] = fmaf(a, b.x, acc[i][0]);
                acc[i][1] = fmaf(a, b.y, acc[i][1]);
                acc[i][2] = fmaf(a, b.z, acc[i][2]);
                acc[i][3] = fmaf(a, b.w, acc[i][3]);
            }
        }
        __syncthreads();
    }

    const float4 bv = *(const float4*)(bias + c0);
#pragma unroll
    for (int i = 0; i < 8; i++) {
        float4 o;
        o.x = acc[i][0] + bv.x;
        o.y = acc[i][1] + bv.y;
        o.z = acc[i][2] + bv.z;
        o.w = acc[i][3] + bv.w;
        if (RELU) {
            o.x = fmaxf(o.x, 0.f); o.y = fmaxf(o.y, 0.f);
            o.z = fmaxf(o.z, 0.f); o.w = fmaxf(o.w, 0.f);
        }
        const size_t off = (size_t)(row0 + r0 + i) * 128 + c0;
        *(float4*)(out + off) = o;
        if (DUAL) *(float4*)(out2 + off) = o;
    }
}

// ---------------- fused GIN nn + score dots -------------------------------
// out = relu(A@Wa+ba) @ Wb + bb, then per-row srel = h.Wrel, sroot = h.Wroot
// (float4 lane dot + butterfly reduce — identical structure to the R11
// score_pre kernel), lane0 writes srel/sroot and zeroes ssum.
__global__ void __launch_bounds__(256) gin_kernel(const float* __restrict__ A,
                                                  const float* __restrict__ Wa,
                                                  const float* __restrict__ ba,
                                                  const float* __restrict__ Wb,
                                                  const float* __restrict__ bb,
                                                  float* __restrict__ out,
                                                  const float* __restrict__ Wrel,
                                                  const float* __restrict__ Wroot,
                                                  float* __restrict__ srel,
                                                  float* __restrict__ sroot,
                                                  float* __restrict__ ssum) {
    extern __shared__ char smem[];
    float (*As)[36]  = (float(*)[36])smem;                    //  9216 B
    float (*Bs)[128] = (float(*)[128])(smem + 9216);          // 16384 B
    float (*T1)[132] = (float(*)[132])(smem + 9216 + 16384);  // 33792 B

    const int tid  = threadIdx.x;
    const int row0 = blockIdx.x * 64;
    const int warp = tid >> 5, lane = tid & 31;
    const int r0 = warp * 8;
    const int c0 = lane * 4;

    float acc[8][4];
#pragma unroll
    for (int i = 0; i < 8; i++)
#pragma unroll
        for (int j = 0; j < 4; j++) acc[i][j] = 0.f;

    // ---- phase 1: t1 = relu(A@Wa + ba)
    for (int k0 = 0; k0 < CC_; k0 += 32) {
        {
            const int r  = tid >> 3;
            const int k4 = (tid & 7) * 4;
            float4 v0 = *(const float4*)(A + (size_t)(row0 + r) * CC_ + k0 + k4);
            float4 v1 = *(const float4*)(A + (size_t)(row0 + r + 32) * CC_ + k0 + k4);
            *(float4*)&As[r][k4]      = v0;
            *(float4*)&As[r + 32][k4] = v1;
        }
#pragma unroll
        for (int it = 0; it < 4; ++it) {
            const int f  = tid + it * 256;
            const int k  = f >> 5;
            const int c4 = (f & 31) * 4;
            *(float4*)&Bs[k][c4] = *(const float4*)(Wa + (size_t)(k0 + k) * 128 + c4);
        }
        __syncthreads();
#pragma unroll
        for (int kk = 0; kk < 32; ++kk) {
            const float4 b = *(const float4*)&Bs[kk][c0];
#pragma unroll
            for (int i = 0; i < 8; i++) {
                const float a = As[r0 + i][kk];
                acc[i][0] = fmaf(a, b.x, acc[i][0]);
                acc[i][1] = fmaf(a, b.y, acc[i][1]);
                acc[i][2] = fmaf(a, b.z, acc[i][2]);
                acc[i][3] = fmaf(a, b.w, acc[i][3]);
            }
        }
        __syncthreads();
    }
    {
        const float4 bv = *(const float4*)(ba + c0);
#pragma unroll
        for (int i = 0; i < 8; i++) {
            float4 o;
            o.x = fmaxf(acc[i][0] + bv.x, 0.f);
            o.y = fmaxf(acc[i][1] + bv.y, 0.f);
            o.z = fmaxf(acc[i][2] + bv.z, 0.f);
            o.w = fmaxf(acc[i][3] + bv.w, 0.f);
            *(float4*)&T1[r0 + i][c0] = o;
        }
    }

    // ---- phase 2: out = t1 @ Wb + bb
#pragma unroll
    for (int i = 0; i < 8; i++)
#pragma unroll
        for (int j = 0; j < 4; j++) acc[i][j] = 0.f;

    for (int k0 = 0; k0 < CC_; k0 += 32) {
#pragma unroll
        for (int it = 0; it < 4; ++it) {
            const int f  = tid + it * 256;
            const int k  = f >> 5;
            const int c4 = (f & 31) * 4;
            *(float4*)&Bs[k][c4] = *(const float4*)(Wb + (size_t)(k0 + k) * 128 + c4);
        }
        __syncthreads();   // also orders T1 writes before T1 reads (k0 == 0)
#pragma unroll
        for (int kk = 0; kk < 32; ++kk) {
            const float4 b = *(const float4*)&Bs[kk][c0];
#pragma unroll
            for (int i = 0; i < 8; i++) {
                const float a = T1[r0 + i][k0 + kk];
                acc[i][0] = fmaf(a, b.x, acc[i][0]);
                acc[i][1] = fmaf(a, b.y, acc[i][1]);
                acc[i][2] = fmaf(a, b.z, acc[i][2]);
                acc[i][3] = fmaf(a, b.w, acc[i][3]);
            }
        }
        __syncthreads();
    }
    {
        const float4 bv = *(const float4*)(bb + c0);
        const float4 wr = *(const float4*)(Wrel + c0);
        const float4 wt = *(const float4*)(Wroot + c0);
#pragma unroll
        for (int i = 0; i < 8; i++) {
            float4 o;
            o.x = acc[i][0] + bv.x;
            o.y = acc[i][1] + bv.y;
            o.z = acc[i][2] + bv.z;
            o.w = acc[i][3] + bv.w;
            *(float4*)(out + (size_t)(row0 + r0 + i) * 128 + c0) = o;
            // score dots (same structure as R11 score_pre)
            float t1 = o.x * wr.x + o.y * wr.y + o.z * wr.z + o.w * wr.w;
            float t2 = o.x * wt.x + o.y * wt.y + o.z * wt.z + o.w * wt.w;
#pragma unroll
            for (int of = 16; of > 0; of >>= 1) {
                t1 += __shfl_xor_sync(0xffffffffu, t1, of);
                t2 += __shfl_xor_sync(0xffffffffu, t2, of);
            }
            if (lane == 0) {
                const int row = row0 + r0 + i;
                srel[row] = t1;
                sroot[row] = t2;
                ssum[row] = 0.f;
            }
        }
    }
}
#define GIN_SMEM (9216 + 16384 + 33792)

// ---------------- edge vector scatter-add (8 edges / warp, MLP=8) ---------
// If newid != nullptr, edge endpoints are remapped through it; an edge is
// valid iff both remapped ids are >= 0 (layer-2 pooled graph).
#define SCAT_EPW 8
__global__ void scatter_kernel(const float* __restrict__ x, const int* __restrict__ src,
                               const int* __restrict__ dst,
                               const int* __restrict__ newid,
                               float* __restrict__ agg, int nE) {
    const int w = (blockIdx.x * blockDim.x + threadIdx.x) >> 5;
    const int lane = threadIdx.x & 31;
    const int e0 = w * SCAT_EPW;
    if (e0 >= nE) return;
    float4 v[SCAT_EPW];
    int d[SCAT_EPW];
    bool ok[SCAT_EPW];
#pragma unroll
    for (int i = 0; i < SCAT_EPW; i++) {
        const int e = e0 + i;
        ok[i] = (e < nE);
        if (ok[i]) {
            int s = src[e];
            d[i] = dst[e];
            if (newid) {
                s = newid[s];
                d[i] = newid[d[i]];
                ok[i] = (s >= 0) && (d[i] >= 0);
            }
            if (ok[i]) v[i] = *(const float4*)(x + (size_t)s * CC_ + lane * 4);
        }
    }
#pragma unroll
    for (int i = 0; i < SCAT_EPW; i++)
        if (ok[i])
            atomicAdd((float4*)(agg + (size_t)d[i] * CC_ + lane * 4), v[i]);
}

// ---------------- scalar edge scatter-add for scores (4 edges / thread) ---
__global__ void scatter_scalar_kernel(const float* __restrict__ srel,
                                      const int* __restrict__ src,
                                      const int* __restrict__ dst,
                                      const int* __restrict__ newid,
                                      float* __restrict__ ssum, int nE) {
    const int t = blockIdx.x * blockDim.x + threadIdx.x;
    const int e0 = t * 4;
    if (e0 >= nE) return;
    int4 s4 = *(const int4*)(src + e0);
    int4 d4 = *(const int4*)(dst + e0);
    bool m0 = true, m1 = true, m2 = true, m3 = true;
    if (newid) {
        s4.x = newid[s4.x]; d4.x = newid[d4.x]; m0 = (s4.x >= 0) && (d4.x >= 0);
        s4.y = newid[s4.y]; d4.y = newid[d4.y]; m1 = (s4.y >= 0) && (d4.y >= 0);
        s4.z = newid[s4.z]; d4.z = newid[d4.z]; m2 = (s4.z >= 0) && (d4.z >= 0);
        s4.w = newid[s4.w]; d4.w = newid[d4.w]; m3 = (s4.w >= 0) && (d4.w >= 0);
    }
    float a0 = 0.f, a1 = 0.f, a2 = 0.f, a3 = 0.f;
    if (m0) a0 = srel[s4.x];
    if (m1) a1 = srel[s4.y];
    if (m2) a2 = srel[s4.z];
    if (m3) a3 = srel[s4.w];
    if (m0) atomicAdd(&ssum[d4.x], a0);
    if (m1) atomicAdd(&ssum[d4.y], a1);
    if (m2) atomicAdd(&ssum[d4.z], a2);
    if (m3) atomicAdd(&ssum[d4.w], a3);
}

// ---------------- score finalize + composite sort key + inits -------------
__global__ void score_fin_kernel(const float* __restrict__ ssum,
                                 const float* __restrict__ sroot,
                                 const float* __restrict__ brel,
                                 float* __restrict__ scores,
                                 unsigned long long* __restrict__ key64,
                                 int* __restrict__ iota,
                                 int* __restrict__ newid_init,
                                 float* __restrict__ ozero,
                                 int npg, int n) {
    const int node = blockIdx.x * blockDim.x + threadIdx.x;
    if (node >= n) return;
    const float sc = xla_tanh((ssum[node] + brel[0]) + sroot[node]);
    scores[node] = sc;
    unsigned int u = __float_as_uint(sc);
    unsigned int e = (u & 0x80000000u) ? ~u : (u | 0x80000000u); // ascending encode
    unsigned int kd = ~e;                                         // descending
    const unsigned int g = (unsigned int)(node / npg);
    key64[node] = ((unsigned long long)g << 32) | (unsigned long long)kd;
    iota[node] = node;
    if (newid_init) newid_init[node] = -1;
    if (ozero && node < BGR_ * CC_) ozero[node] = 0.f;
}

// ---------------- selection/gather after sort (1 warp / kept node) -------
__global__ void select_kernel(const float* __restrict__ scores, const int* __restrict__ sidx,
                              const float* __restrict__ xin, float* __restrict__ xout,
                              float* __restrict__ xout2,
                              int* __restrict__ newid, int npg, int k) {
    const int j = blockIdx.x * 8 + (threadIdx.x >> 5);
    if (j >= BGR_ * k) return;
    const int g = j / k, jj = j - g * k;
    const int srcpos = g * npg + jj;
    const int orig = sidx[srcpos];
    const float val = scores[orig];
    const int lane = threadIdx.x & 31;
    float4 v = *(const float4*)(xin + (size_t)orig * CC_ + lane * 4);
    v.x *= val; v.y *= val; v.z *= val; v.w *= val;
    const size_t off = (size_t)j * CC_ + lane * 4;
    *(float4*)(xout + off) = v;
    if (xout2) *(float4*)(xout2 + off) = v;
    if (lane == 0) newid[orig] = j;
}

// ---------------- per-graph mean pooling: parallel partial sums ----------
#define MEAN_BPG 16
__global__ void mean_part_kernel(const float* __restrict__ x, float* __restrict__ out, int k) {
    const int b = blockIdx.x / MEAN_BPG;
    const int chunk = blockIdx.x % MEAN_BPG;
    const int rows = (k + MEAN_BPG - 1) / MEAN_BPG;
    const int r0 = chunk * rows;
    const int r1 = (r0 + rows < k) ? (r0 + rows) : k;
    const int col = threadIdx.x;  // 0..127
    float s = 0.f;
    for (int r = r0; r < r1; ++r)
        s += x[((size_t)b * k + r) * CC_ + col];
    atomicAdd(&out[b * CC_ + col], s);
}

// ---------------- final MLP head (single block) ----------------
__global__ void head_kernel(const float* __restrict__ out1, const float* __restrict__ out2,
                            const float* __restrict__ Wg, const float* __restrict__ bg,
                            const float* __restrict__ Wr1, const float* __restrict__ br1,
                            const float* __restrict__ gg1, const float* __restrict__ be1,
                            const float* __restrict__ Wr2, const float* __restrict__ br2,
                            const float* __restrict__ gg2, const float* __restrict__ be2,
                            const float* __restrict__ Wout, float* __restrict__ out) {
    __shared__ float cat[8][256];
    __shared__ float gmat[8][128];
    __shared__ float r1[8][64];
    __shared__ float r2[8][32];
    const int tid = threadIdx.x;  // 256 threads
    for (int i = tid; i < 8 * 128; i += 256) {
        const int b = i >> 7, c = i & 127;
        cat[b][c]       = out1[i] / (float)KK1_;
        cat[b][c + 128] = out2[i] / (float)KK2_;
    }
    __syncthreads();
    const float inv = 1.0f / sqrtf(1.0f + 1e-5f);
    if (tid < 128) {
        for (int b = 0; b < 8; b++) {
            float s = 0.f;
            for (int k = 0; k < 256; k++) s = fmaf(cat[b][k], Wg[k * 128 + tid], s);
            gmat[b][tid] = s + bg[tid];
        }
    }
    __syncthreads();
    if (tid < 64) {
        for (int b = 0; b < 8; b++) {
            float s = 0.f;
            for (int k = 0; k < 128; k++) s = fmaf(gmat[b][k], Wr1[k * 64 + tid], s);
            s = (s + br1[tid]) * inv * gg1[tid] + be1[tid];
            r1[b][tid] = fmaxf(s, 0.f);
        }
    }
    __syncthreads();
    if (tid < 32) {
        for (int b = 0; b < 8; b++) {
            float s = 0.f;
            for (int k = 0; k < 64; k++) s = fmaf(r1[b][k], Wr2[k * 32 + tid], s);
            s = (s + br2[tid]) * inv * gg2[tid] + be2[tid];
            r2[b][tid] = fmaxf(s, 0.f);
        }
    }
    __syncthreads();
    if (tid < 32) {
        const int b = tid >> 2, j = tid & 3;
        float s = 0.f;
        for (int k = 0; k < 32; k++) s = fmaf(r2[b][k], Wout[k * 4 + j], s);
        out[b * 4 + j] = s;
    }
}

// ---------------- host orchestration ----------------
extern "C" void kernel_launch(void* const* d_in, const int* in_sizes, int n_in,
                              void* d_out, int out_size) {
    const float* x    = (const float*)d_in[0];
    const int*   ei   = (const int*)d_in[1];
    const int*   src  = ei;
    const int*   dst  = ei + EDG_;
    const float* W0   = (const float*)d_in[3];
    const float* b0   = (const float*)d_in[4];
    const float* W1a  = (const float*)d_in[5];
    const float* b1a  = (const float*)d_in[6];
    const float* W1b  = (const float*)d_in[7];
    const float* b1b  = (const float*)d_in[8];
    const float* Wrel1  = (const float*)d_in[9];
    const float* brel1  = (const float*)d_in[10];
    const float* Wroot1 = (const float*)d_in[11];
    const float* W2a  = (const float*)d_in[12];
    const float* b2a  = (const float*)d_in[13];
    const float* W2b  = (const float*)d_in[14];
    const float* b2b  = (const float*)d_in[15];
    const float* Wrel2  = (const float*)d_in[16];
    const float* brel2  = (const float*)d_in[17];
    const float* Wroot2 = (const float*)d_in[18];
    const float* Wg   = (const float*)d_in[19];
    const float* bg   = (const float*)d_in[20];
    const float* Wr1  = (const float*)d_in[21];
    const float* br1  = (const float*)d_in[22];
    const float* gg1  = (const float*)d_in[23];
    const float* be1  = (const float*)d_in[24];
    const float* Wr2  = (const float*)d_in[25];
    const float* br2  = (const float*)d_in[26];
    const float* gg2  = (const float*)d_in[27];
    const float* be2  = (const float*)d_in[28];
    const float* Wout = (const float*)d_in[29];

    float *bufA, *bufB, *bufC, *scores, *srel, *sroot, *ssum, *o1, *o2;
    unsigned long long *key64, *key64B;
    int *iota, *sidx, *newid;
    unsigned char *cubtmp;
    cudaGetSymbolAddress((void**)&bufA, g_bufA);
    cudaGetSymbolAddress((void**)&bufB, g_bufB);
    cudaGetSymbolAddress((void**)&bufC, g_bufC);
    cudaGetSymbolAddress((void**)&scores, g_scores);
    cudaGetSymbolAddress((void**)&srel, g_srel);
    cudaGetSymbolAddress((void**)&sroot, g_sroot);
    cudaGetSymbolAddress((void**)&ssum, g_ssum);
    cudaGetSymbolAddress((void**)&key64, g_key64);
    cudaGetSymbolAddress((void**)&key64B, g_key64B);
    cudaGetSymbolAddress((void**)&iota, g_iota);
    cudaGetSymbolAddress((void**)&sidx, g_sidx);
    cudaGetSymbolAddress((void**)&newid, g_newid);
    cudaGetSymbolAddress((void**)&o1, g_out1);
    cudaGetSymbolAddress((void**)&o2, g_out2);
    cudaGetSymbolAddress((void**)&cubtmp, g_cubtmp);

    cudaFuncSetAttribute(gin_kernel, cudaFuncAttributeMaxDynamicSharedMemorySize, GIN_SMEM);

    const int scat_blocks = (EDG_ + SCAT_EPW * 8 - 1) / (SCAT_EPW * 8);

    // ---- stage 0: h0 = relu(x @ W0 + b0) -> bufA AND bufB (scatter base)
    gemm_kernel<FF_, true, true><<<NB_ / 64, 256>>>(x, W0, b0, bufA, bufB);

    // ---- GIN layer 1: bufB += segsum(h0) ; h1 = gin(bufB), + score dots
    scatter_kernel<<<scat_blocks, 256>>>(bufA, src, dst, nullptr, bufB, EDG_);
    gin_kernel<<<NB_ / 64, 256, GIN_SMEM>>>(bufB, W1a, b1a, W1b, b1b, bufB,
                                            Wrel1, Wroot1, srel, sroot, ssum);  // h1 = bufB

    // ---- SAGPool 1
    scatter_scalar_kernel<<<(EDG_ / 4 + 255) / 256, 256>>>(srel, src, dst, nullptr, ssum, EDG_);
    score_fin_kernel<<<(NB_ + 255) / 256, 256>>>(ssum, sroot, brel1, scores, key64, iota,
                                                 newid, o1, NPG_, NB_);
    {
        size_t tmp = 0;
        cub::DeviceRadixSort::SortPairs(nullptr, tmp, key64, key64B, iota, sidx, NB_, 0, 35);
        if (tmp > sizeof(g_cubtmp)) tmp = sizeof(g_cubtmp);
        cub::DeviceRadixSort::SortPairs((void*)cubtmp, tmp, key64, key64B, iota, sidx, NB_, 0, 35);
    }
    // h2 -> bufC AND bufA (layer-2 scatter base)
    select_kernel<<<NB1_ / 8, 256>>>(scores, sidx, bufB, bufC, bufA, newid, NPG_, KK1_);
    mean_part_kernel<<<BGR_ * MEAN_BPG, 128>>>(bufC, o1, KK1_);

    // ---- GIN layer 2: bufA += segsum(h2, via newid remap) ; h3 = gin(bufA)
    scatter_kernel<<<scat_blocks, 256>>>(bufC, src, dst, newid, bufA, EDG_);
    gin_kernel<<<NB1_ / 64, 256, GIN_SMEM>>>(bufA, W2a, b2a, W2b, b2b, bufC,
                                             Wrel2, Wroot2, srel, sroot, ssum);  // h3 = bufC

    // ---- SAGPool 2
    scatter_scalar_kernel<<<(EDG_ / 4 + 255) / 256, 256>>>(srel, src, dst, newid, ssum, EDG_);
    score_fin_kernel<<<(NB1_ + 255) / 256, 256>>>(ssum, sroot, brel2, scores, key64, iota,
                                                  nullptr, o2, KK1_, NB1_);
    {
        size_t tmp = 0;
        cub::DeviceRadixSort::SortPairs(nullptr, tmp, key64, key64B, iota, sidx, NB1_, 0, 35);
        if (tmp > sizeof(g_cubtmp)) tmp = sizeof(g_cubtmp);
        cub::DeviceRadixSort::SortPairs((void*)cubtmp, tmp, key64, key64B, iota, sidx, NB1_, 0, 35);
    }
    select_kernel<<<NB2_ / 8, 256>>>(scores, sidx, bufC, bufB, nullptr, newid, KK1_, KK2_);
    mean_part_kernel<<<BGR_ * MEAN_BPG, 128>>>(bufB, o2, KK2_);

    // ---- head
    head_kernel<<<1, 256>>>(o1, o2, Wg, bg, Wr1, br1, gg1, be1,
                            Wr2, br2, gg2, be2, Wout, (float*)d_out);
}